// round 1
// baseline (speedup 1.0000x reference)
#include <cuda_runtime.h>
#include <cuda_bf16.h>

// Problem constants
#define Bdim 4
#define Sdim 2048
#define Cdim 1024
#define NH   16
#define HD   64
#define Mrows (Bdim * Sdim)   // 8192

// Scratch (allocation-free rule: __device__ globals)
__device__ float g_q[Bdim * NH * Sdim * HD];
__device__ float g_k[Bdim * NH * Sdim * HD];
__device__ float g_v[Bdim * NH * Sdim * HD];
__device__ float g_att[Bdim * NH * Sdim * HD];

// ---------------------------------------------------------------------------
// SGEMM: C[m][n] = sum_k A[m][k] * W[n][k] + bias[n]
// BM=128, BN=128, BK=16, 256 threads, 8x8 per thread.
// MODE 0: A = x (plain), write g_q in [b][h][s][d]
// MODE 1: A = y (plain), write g_k / g_v (n<1024 -> k, else v)
// MODE 2: A = g_att read permuted from [b][h][s][d], write out plain [m][n]
// ---------------------------------------------------------------------------
#define BM 128
#define BN 128
#define BKK 16

template <int MODE>
__global__ __launch_bounds__(256)
void gemm_k(const float* __restrict__ A, const float* __restrict__ W,
            const float* __restrict__ bias, float* __restrict__ out,
            int Ndim, int Kdim)
{
    __shared__ __align__(16) float As[BKK][BM];
    __shared__ __align__(16) float Bs[BKK][BN];

    const int tid = threadIdx.x;
    const int tx = tid & 15;        // 0..15 -> column tile
    const int ty = tid >> 4;        // 0..15 -> row tile
    const int m0 = blockIdx.y * BM;
    const int n0 = blockIdx.x * BN;

    const int lrow = tid >> 2;          // 0..63
    const int lcol = (tid & 3) * 4;     // 0,4,8,12

    float acc[8][8];
#pragma unroll
    for (int i = 0; i < 8; ++i)
#pragma unroll
        for (int j = 0; j < 8; ++j) acc[i][j] = 0.f;

    for (int k0 = 0; k0 < Kdim; k0 += BKK) {
        // Load A tile (BM x BK), store transposed As[k][m]
#pragma unroll
        for (int r = 0; r < BM; r += 64) {
            const int m = m0 + lrow + r;
            float4 t;
            if (MODE == 2) {
                const int bb = m >> 11;            // m / S
                const int ss = m & (Sdim - 1);
                const int k = k0 + lcol;
                const int hh = k >> 6, dd = k & 63;
                t = *(const float4*)(g_att +
                        ((((size_t)bb * NH + hh) * Sdim + ss) * HD + dd));
            } else {
                t = *(const float4*)(A + (size_t)m * Kdim + k0 + lcol);
            }
            As[lcol + 0][lrow + r] = t.x;
            As[lcol + 1][lrow + r] = t.y;
            As[lcol + 2][lrow + r] = t.z;
            As[lcol + 3][lrow + r] = t.w;
        }
        // Load W tile (BN x BK), store transposed Bs[k][n]
#pragma unroll
        for (int r = 0; r < BN; r += 64) {
            const int n = n0 + lrow + r;
            float4 t = *(const float4*)(W + (size_t)n * Kdim + k0 + lcol);
            Bs[lcol + 0][lrow + r] = t.x;
            Bs[lcol + 1][lrow + r] = t.y;
            Bs[lcol + 2][lrow + r] = t.z;
            Bs[lcol + 3][lrow + r] = t.w;
        }
        __syncthreads();

#pragma unroll
        for (int kk = 0; kk < BKK; ++kk) {
            float ar[8], br[8];
            *(float4*)(ar + 0) = *(const float4*)(&As[kk][ty * 8 + 0]);
            *(float4*)(ar + 4) = *(const float4*)(&As[kk][ty * 8 + 4]);
            *(float4*)(br + 0) = *(const float4*)(&Bs[kk][tx * 8 + 0]);
            *(float4*)(br + 4) = *(const float4*)(&Bs[kk][tx * 8 + 4]);
#pragma unroll
            for (int i = 0; i < 8; ++i)
#pragma unroll
                for (int j = 0; j < 8; ++j)
                    acc[i][j] += ar[i] * br[j];
        }
        __syncthreads();
    }

    // Epilogue
#pragma unroll
    for (int i = 0; i < 8; ++i) {
        const int m = m0 + ty * 8 + i;
        const int bb = m >> 11;
        const int ss = m & (Sdim - 1);
#pragma unroll
        for (int j = 0; j < 8; ++j) {
            const int n = n0 + tx * 8 + j;
            const float v = acc[i][j] + bias[n];
            if (MODE == 0) {
                const int hh = n >> 6, dd = n & 63;
                g_q[(((size_t)bb * NH + hh) * Sdim + ss) * HD + dd] = v;
            } else if (MODE == 1) {
                const int sel = n >> 10;
                const int r = n & 1023;
                const int hh = r >> 6, dd = r & 63;
                float* dst = sel ? g_v : g_k;
                dst[(((size_t)bb * NH + hh) * Sdim + ss) * HD + dd] = v;
            } else {
                out[(size_t)m * Ndim + n] = v;
            }
        }
    }
}

// ---------------------------------------------------------------------------
// Flash-style causal attention, fp32.
// Grid: (S/128, NH, B), block 128 threads, 1 query per thread, 32-key tiles.
// ---------------------------------------------------------------------------
__global__ __launch_bounds__(128)
void attn_k(const unsigned char* __restrict__ mask)
{
    const int q = blockIdx.x * 128 + threadIdx.x;
    const int h = blockIdx.y;
    const int b = blockIdx.z;

    __shared__ __align__(16) float Ks[32][64];
    __shared__ __align__(16) float Vs[32][64];

    const float* qptr = g_q + (((size_t)b * NH + h) * Sdim + q) * HD;
    float qr[64];
#pragma unroll
    for (int d = 0; d < 64; d += 4)
        *(float4*)(qr + d) = *(const float4*)(qptr + d);
#pragma unroll
    for (int d = 0; d < 64; ++d) qr[d] *= 0.125f;   // 1/sqrt(64)

    float accv[64];
#pragma unroll
    for (int d = 0; d < 64; ++d) accv[d] = 0.f;
    float mrun = -1e30f;
    float lrun = 0.f;

    const unsigned char* mrow = mask + (size_t)b * Sdim;
    const float* kbase = g_k + (((size_t)b * NH + h) * Sdim) * HD;
    const float* vbase = g_v + (((size_t)b * NH + h) * Sdim) * HD;
    const int kend = blockIdx.x * 128 + 128;   // max key needed in this block

    for (int k0 = 0; k0 < kend; k0 += 32) {
        // Cooperative load of K/V tiles (32x64 floats each)
#pragma unroll
        for (int it = 0; it < 4; ++it) {
            const int e = (it * 128 + threadIdx.x) * 4;
            *(float4*)(&Ks[0][0] + e) = *(const float4*)(kbase + (size_t)k0 * HD + e);
            *(float4*)(&Vs[0][0] + e) = *(const float4*)(vbase + (size_t)k0 * HD + e);
        }
        __syncthreads();

        float s[32];
#pragma unroll
        for (int j = 0; j < 32; ++j) {
            const int kk = k0 + j;
            float sc = 0.f;
#pragma unroll
            for (int d4 = 0; d4 < 64; d4 += 4) {
                const float4 kv = *(const float4*)(&Ks[j][d4]);
                sc += qr[d4 + 0] * kv.x;
                sc += qr[d4 + 1] * kv.y;
                sc += qr[d4 + 2] * kv.z;
                sc += qr[d4 + 3] * kv.w;
            }
            const bool valid = (kk <= q) && (mrow[kk] == 0);
            s[j] = valid ? sc : -1e30f;
        }

        float tmax = s[0];
#pragma unroll
        for (int j = 1; j < 32; ++j) tmax = fmaxf(tmax, s[j]);
        const float mnew = fmaxf(mrun, tmax);

        if (mnew > -1e29f) {
            const float corr = __expf(mrun - mnew);   // underflows to 0 on first tile
            lrun *= corr;
#pragma unroll
            for (int d = 0; d < 64; ++d) accv[d] *= corr;
#pragma unroll
            for (int j = 0; j < 32; ++j) {
                const float p = __expf(s[j] - mnew);
                lrun += p;
#pragma unroll
                for (int d4 = 0; d4 < 64; d4 += 4) {
                    const float4 vv = *(const float4*)(&Vs[j][d4]);
                    accv[d4 + 0] += p * vv.x;
                    accv[d4 + 1] += p * vv.y;
                    accv[d4 + 2] += p * vv.z;
                    accv[d4 + 3] += p * vv.w;
                }
            }
            mrun = mnew;
        }
        __syncthreads();
    }

    const float inv = 1.f / lrun;
    float* op = g_att + (((size_t)b * NH + h) * Sdim + q) * HD;
#pragma unroll
    for (int d = 0; d < 64; d += 4) {
        float4 o;
        o.x = accv[d + 0] * inv;
        o.y = accv[d + 1] * inv;
        o.z = accv[d + 2] * inv;
        o.w = accv[d + 3] * inv;
        *(float4*)(op + d) = o;
    }
}

// ---------------------------------------------------------------------------
extern "C" void kernel_launch(void* const* d_in, const int* in_sizes, int n_in,
                              void* d_out, int out_size)
{
    const float* x     = (const float*)d_in[0];
    const float* y     = (const float*)d_in[1];
    const unsigned char* mask = (const unsigned char*)d_in[2];
    const float* Wq_w  = (const float*)d_in[3];
    const float* Wq_b  = (const float*)d_in[4];
    const float* Wkv_w = (const float*)d_in[5];
    const float* Wkv_b = (const float*)d_in[6];
    const float* Wo_w  = (const float*)d_in[7];
    const float* Wo_b  = (const float*)d_in[8];
    float* out = (float*)d_out;

    // Q projection: [8192,1024] x [1024,1024]^T -> g_q
    gemm_k<0><<<dim3(Cdim / BN, Mrows / BM), 256>>>(x, Wq_w, Wq_b, nullptr,
                                                    Cdim, Cdim);
    // KV projection: [8192,1024] x [2048,1024]^T -> g_k, g_v
    gemm_k<1><<<dim3(2 * Cdim / BN, Mrows / BM), 256>>>(y, Wkv_w, Wkv_b, nullptr,
                                                        2 * Cdim, Cdim);
    // Causal attention -> g_att
    attn_k<<<dim3(Sdim / 128, NH, Bdim), 128>>>(mask);
    // Output projection: g_att (permuted) x [1024,1024]^T -> out
    gemm_k<2><<<dim3(Cdim / BN, Mrows / BM), 256>>>(nullptr, Wo_w, Wo_b, out,
                                                    Cdim, Cdim);
}

// round 5
// speedup vs baseline: 1.2931x; 1.2931x over previous
#include <cuda_runtime.h>
#include <cuda_bf16.h>
#include <cstdint>

// Problem constants
#define Bdim 4
#define Sdim 2048
#define Cdim 1024
#define NH   16
#define HD   64
#define Mrows (Bdim * Sdim)   // 8192

// ---------------------------------------------------------------------------
// Scratch (__device__ globals; referenced ONLY from device code)
// ---------------------------------------------------------------------------
__device__ float g_q[Bdim * NH * Sdim * HD];
__device__ float g_k[Bdim * NH * Sdim * HD];
__device__ float g_v[Bdim * NH * Sdim * HD];

__device__ __align__(16) __nv_bfloat16 g_xh[Mrows * Cdim];
__device__ __align__(16) __nv_bfloat16 g_xl[Mrows * Cdim];
__device__ __align__(16) __nv_bfloat16 g_yh[Mrows * Cdim];
__device__ __align__(16) __nv_bfloat16 g_yl[Mrows * Cdim];
__device__ __align__(16) __nv_bfloat16 g_ath[Mrows * Cdim];
__device__ __align__(16) __nv_bfloat16 g_atl[Mrows * Cdim];
__device__ __align__(16) __nv_bfloat16 g_wqh[Cdim * Cdim];
__device__ __align__(16) __nv_bfloat16 g_wql[Cdim * Cdim];
__device__ __align__(16) __nv_bfloat16 g_wkvh[2 * Cdim * Cdim];
__device__ __align__(16) __nv_bfloat16 g_wkvl[2 * Cdim * Cdim];
__device__ __align__(16) __nv_bfloat16 g_woh[Cdim * Cdim];
__device__ __align__(16) __nv_bfloat16 g_wol[Cdim * Cdim];

// ---------------------------------------------------------------------------
// PTX helpers (base sm_103 ISA: cp.async, ldmatrix, mma.sync)
// ---------------------------------------------------------------------------
__device__ __forceinline__ uint32_t smem_u32(const void* p) {
    uint32_t a;
    asm("{ .reg .u64 t; cvta.to.shared.u64 t, %1; cvt.u32.u64 %0, t; }"
        : "=r"(a) : "l"(p));
    return a;
}

#define CP_ASYNC16(sa, ga) \
    asm volatile("cp.async.cg.shared.global [%0], [%1], 16;" :: "r"(sa), "l"(ga) : "memory")
#define CP_COMMIT() asm volatile("cp.async.commit_group;" ::: "memory")
#define CP_WAIT(n)  asm volatile("cp.async.wait_group %0;" :: "n"(n) : "memory")

__device__ __forceinline__ void ldsm_x4(uint32_t* r, uint32_t addr) {
    asm volatile("ldmatrix.sync.aligned.m8n8.x4.shared.b16 {%0,%1,%2,%3}, [%4];"
                 : "=r"(r[0]), "=r"(r[1]), "=r"(r[2]), "=r"(r[3]) : "r"(addr));
}
__device__ __forceinline__ void mma_bf16(float* d, const uint32_t* a, const uint32_t* b) {
    asm volatile("mma.sync.aligned.m16n8k16.row.col.f32.bf16.bf16.f32 "
                 "{%0,%1,%2,%3}, {%4,%5,%6,%7}, {%8,%9}, {%0,%1,%2,%3};"
                 : "+f"(d[0]), "+f"(d[1]), "+f"(d[2]), "+f"(d[3])
                 : "r"(a[0]), "r"(a[1]), "r"(a[2]), "r"(a[3]), "r"(b[0]), "r"(b[1]));
}

// ---------------------------------------------------------------------------
// fp32 -> bf16 hi/lo split. T selects destination (device globals, referenced
// in device code only).
// ---------------------------------------------------------------------------
template <int T>
__global__ __launch_bounds__(256)
void split_k(const float4* __restrict__ in, int n4)
{
    __nv_bfloat162* hi;
    __nv_bfloat162* lo;
    if (T == 0)      { hi = (__nv_bfloat162*)g_xh;  lo = (__nv_bfloat162*)g_xl;  }
    else if (T == 1) { hi = (__nv_bfloat162*)g_yh;  lo = (__nv_bfloat162*)g_yl;  }
    else if (T == 2) { hi = (__nv_bfloat162*)g_wqh; lo = (__nv_bfloat162*)g_wql; }
    else if (T == 3) { hi = (__nv_bfloat162*)g_wkvh;lo = (__nv_bfloat162*)g_wkvl;}
    else             { hi = (__nv_bfloat162*)g_woh; lo = (__nv_bfloat162*)g_wol; }

    const int i = blockIdx.x * 256 + threadIdx.x;
    if (i >= n4) return;
    const float4 v = in[i];
    const __nv_bfloat16 h0 = __float2bfloat16(v.x);
    const __nv_bfloat16 h1 = __float2bfloat16(v.y);
    const __nv_bfloat16 h2 = __float2bfloat16(v.z);
    const __nv_bfloat16 h3 = __float2bfloat16(v.w);
    hi[2 * i + 0] = __nv_bfloat162(h0, h1);
    hi[2 * i + 1] = __nv_bfloat162(h2, h3);
    lo[2 * i + 0] = __nv_bfloat162(__float2bfloat16(v.x - __bfloat162float(h0)),
                                   __float2bfloat16(v.y - __bfloat162float(h1)));
    lo[2 * i + 1] = __nv_bfloat162(__float2bfloat16(v.z - __bfloat162float(h2)),
                                   __float2bfloat16(v.w - __bfloat162float(h3)));
}

// ---------------------------------------------------------------------------
// HMMA GEMM: C[m][n] = sum_k A[m][k]*W[n][k] + bias[n]
// 3-term bf16 split: Ah*Wh + Al*Wh + Ah*Wl.  A/B selected per MODE from
// device globals (in device code).
// CTA tile 128x128, K stage 16, double-buffered cp.async, 32KB static smem.
// Tile layout: chunk-column-major, byte off = chunk*2048 + row*16
//   (chunk = 8 bf16 of k). ldmatrix reads 8 consecutive rows = 128B
//   contiguous -> conflict-free, no swizzle.
// 8 warps: 2(M) x 4(N); warp tile 64x32 = 4x4 mma(16x8) tiles.
// MODE 0: write fp32 g_q permuted [b,h,s,d]
// MODE 1: write fp32 g_k / g_v permuted (n<1024 -> k, else v)
// MODE 2: write fp32 out plain [m][n]
// ---------------------------------------------------------------------------
#define TILE_BYTES 4096u     // 128 rows * 16 k * 2B
#define BUF_BYTES  16384u    // 4 tiles
#define NSTAGE     64        // K = 1024 / 16

template <int MODE>
__global__ __launch_bounds__(256)
void gemm_tc(const float* __restrict__ bias, float* __restrict__ out)
{
    const __nv_bfloat16 *Ah, *Al, *Bh, *Bl;
    if (MODE == 0)      { Ah = g_xh;  Al = g_xl;  Bh = g_wqh;  Bl = g_wql;  }
    else if (MODE == 1) { Ah = g_yh;  Al = g_yl;  Bh = g_wkvh; Bl = g_wkvl; }
    else                { Ah = g_ath; Al = g_atl; Bh = g_woh;  Bl = g_wol;  }

    __shared__ __align__(128) char smraw[2 * BUF_BYTES];   // 32 KB static
    const uint32_t smb = smem_u32(smraw);

    const int tid = threadIdx.x;
    const int wid = tid >> 5;
    const int lane = tid & 31;
    const int m0 = blockIdx.y * 128;
    const int n0 = blockIdx.x * 128;
    const int warp_m = (wid & 1) * 64;
    const int warp_n = (wid >> 1) * 32;

    float acc[4][4][4];
#pragma unroll
    for (int i = 0; i < 4; ++i)
#pragma unroll
        for (int j = 0; j < 4; ++j)
#pragma unroll
            for (int c = 0; c < 4; ++c) acc[i][j][c] = 0.f;

    // per-thread load slot: one 16B chunk per tensor per stage
    const int lrow = tid >> 1;           // 0..127
    const int lch  = tid & 1;            // 0..1

    auto load_stage = [&](int s) {
        const int k0g = s * 16;
        const uint32_t bufb = smb + (uint32_t)(s & 1) * BUF_BYTES;
        const uint32_t sa0 = bufb + (uint32_t)(lch * 2048 + lrow * 16);
#pragma unroll
        for (int t = 0; t < 4; ++t) {
            const __nv_bfloat16* base = (t == 0) ? Ah : (t == 1) ? Al : (t == 2) ? Bh : Bl;
            const int r0 = (t < 2) ? m0 : n0;
            const __nv_bfloat16* g = base + (size_t)(r0 + lrow) * Cdim + k0g + lch * 8;
            CP_ASYNC16(sa0 + (uint32_t)t * TILE_BYTES, g);
        }
        CP_COMMIT();
    };

    load_stage(0);

    for (int s = 0; s < NSTAGE; ++s) {
        if (s + 1 < NSTAGE) { load_stage(s + 1); CP_WAIT(1); }
        else                { CP_WAIT(0); }
        __syncthreads();

        const uint32_t bufb = smb + (uint32_t)(s & 1) * BUF_BYTES;
        const uint32_t bAh = bufb + 0 * TILE_BYTES;
        const uint32_t bAl = bufb + 1 * TILE_BYTES;
        const uint32_t bBh = bufb + 2 * TILE_BYTES;
        const uint32_t bBl = bufb + 3 * TILE_BYTES;

        // A fragments: lanes 0-7 m-rows 0-7/k0-7, 8-15 m-rows 8-15/k0-7,
        //              16-23 m-rows 0-7/k8-15, 24-31 m-rows 8-15/k8-15.
        uint32_t af_h[4][4], af_l[4][4];
        {
            const int arow = warp_m + (lane & 15);
            const int kc = lane >> 4;
#pragma unroll
            for (int tm = 0; tm < 4; ++tm) {
                const uint32_t off = (uint32_t)(kc * 2048 + (arow + tm * 16) * 16);
                ldsm_x4(af_h[tm], bAh + off);
                ldsm_x4(af_l[tm], bAl + off);
            }
        }
        // B fragments: W tile rows are n, k contiguous == col-major B for
        // mma.row.col -> plain ldmatrix. One x4: r0=b0/tile0, r1=b1/tile0,
        // r2=b0/tile1, r3=b1/tile1.
        uint32_t bf_h[4][2], bf_l[4][2];
        {
            const int g = lane >> 3;
            const int nr = (lane & 7) + ((g >> 1) << 3);    // 0..15
            const int kc = g & 1;
#pragma unroll
            for (int half = 0; half < 2; ++half) {
                const int row = warp_n + half * 16 + nr;
                const uint32_t off = (uint32_t)(kc * 2048 + row * 16);
                uint32_t r4[4];
                ldsm_x4(r4, bBh + off);
                bf_h[half * 2 + 0][0] = r4[0]; bf_h[half * 2 + 0][1] = r4[1];
                bf_h[half * 2 + 1][0] = r4[2]; bf_h[half * 2 + 1][1] = r4[3];
                ldsm_x4(r4, bBl + off);
                bf_l[half * 2 + 0][0] = r4[0]; bf_l[half * 2 + 0][1] = r4[1];
                bf_l[half * 2 + 1][0] = r4[2]; bf_l[half * 2 + 1][1] = r4[3];
            }
        }

#pragma unroll
        for (int tm = 0; tm < 4; ++tm)
#pragma unroll
            for (int tn = 0; tn < 4; ++tn) {
                mma_bf16(acc[tm][tn], af_h[tm], bf_h[tn]);
                mma_bf16(acc[tm][tn], af_l[tm], bf_h[tn]);
                mma_bf16(acc[tm][tn], af_h[tm], bf_l[tn]);
            }

        __syncthreads();
    }

    // ---- epilogue
#pragma unroll
    for (int tm = 0; tm < 4; ++tm) {
#pragma unroll
        for (int tn = 0; tn < 4; ++tn) {
            const int rbase = m0 + warp_m + tm * 16 + (lane >> 2);
            const int c = n0 + warp_n + tn * 8 + (lane & 3) * 2;
            const float b0 = bias[c], b1 = bias[c + 1];
#pragma unroll
            for (int half = 0; half < 2; ++half) {
                const int m = rbase + half * 8;
                const float v0 = acc[tm][tn][half * 2 + 0] + b0;
                const float v1 = acc[tm][tn][half * 2 + 1] + b1;
                float* dst;
                if (MODE == 2) {
                    dst = out + (size_t)m * Cdim + c;
                } else {
                    const int bb = m >> 11;
                    const int ss = m & (Sdim - 1);
                    if (MODE == 0) {
                        const int h = c >> 6, dd = c & 63;
                        dst = g_q + (((size_t)bb * NH + h) * Sdim + ss) * HD + dd;
                    } else {
                        const int sel = c >> 10;
                        const int rr = c & 1023;
                        const int h = rr >> 6, dd = rr & 63;
                        dst = (sel ? g_v : g_k) + (((size_t)bb * NH + h) * Sdim + ss) * HD + dd;
                    }
                }
                float2 o; o.x = v0; o.y = v1;
                *(float2*)dst = o;
            }
        }
    }
}

// ---------------------------------------------------------------------------
// Flash-style causal attention, fp32; epilogue writes bf16 hi/lo row-major
// [b*s][h*64+d] for the O projection.
// ---------------------------------------------------------------------------
__global__ __launch_bounds__(128)
void attn_k(const unsigned char* __restrict__ mask)
{
    const int q = blockIdx.x * 128 + threadIdx.x;
    const int h = blockIdx.y;
    const int b = blockIdx.z;

    __shared__ __align__(16) float Ks[32][64];
    __shared__ __align__(16) float Vs[32][64];

    const float* qptr = g_q + (((size_t)b * NH + h) * Sdim + q) * HD;
    float qr[64];
#pragma unroll
    for (int d = 0; d < 64; d += 4)
        *(float4*)(qr + d) = *(const float4*)(qptr + d);
#pragma unroll
    for (int d = 0; d < 64; ++d) qr[d] *= 0.125f;

    float accv[64];
#pragma unroll
    for (int d = 0; d < 64; ++d) accv[d] = 0.f;
    float mrun = -1e30f;
    float lrun = 0.f;

    const unsigned char* mrow = mask + (size_t)b * Sdim;
    const float* kbase = g_k + (((size_t)b * NH + h) * Sdim) * HD;
    const float* vbase = g_v + (((size_t)b * NH + h) * Sdim) * HD;
    const int kend = blockIdx.x * 128 + 128;

    for (int k0 = 0; k0 < kend; k0 += 32) {
#pragma unroll
        for (int it = 0; it < 4; ++it) {
            const int e = (it * 128 + threadIdx.x) * 4;
            *(float4*)(&Ks[0][0] + e) = *(const float4*)(kbase + (size_t)k0 * HD + e);
            *(float4*)(&Vs[0][0] + e) = *(const float4*)(vbase + (size_t)k0 * HD + e);
        }
        __syncthreads();

        float s[32];
#pragma unroll
        for (int j = 0; j < 32; ++j) {
            const int kk = k0 + j;
            float sc = 0.f;
#pragma unroll
            for (int d4 = 0; d4 < 64; d4 += 4) {
                const float4 kv = *(const float4*)(&Ks[j][d4]);
                sc += qr[d4 + 0] * kv.x;
                sc += qr[d4 + 1] * kv.y;
                sc += qr[d4 + 2] * kv.z;
                sc += qr[d4 + 3] * kv.w;
            }
            const bool valid = (kk <= q) && (mrow[kk] == 0);
            s[j] = valid ? sc : -1e30f;
        }

        float tmax = s[0];
#pragma unroll
        for (int j = 1; j < 32; ++j) tmax = fmaxf(tmax, s[j]);
        const float mnew = fmaxf(mrun, tmax);

        if (mnew > -1e29f) {
            const float corr = __expf(mrun - mnew);
            lrun *= corr;
#pragma unroll
            for (int d = 0; d < 64; ++d) accv[d] *= corr;
#pragma unroll
            for (int j = 0; j < 32; ++j) {
                const float p = __expf(s[j] - mnew);
                lrun += p;
#pragma unroll
                for (int d4 = 0; d4 < 64; d4 += 4) {
                    const float4 vv = *(const float4*)(&Vs[j][d4]);
                    accv[d4 + 0] += p * vv.x;
                    accv[d4 + 1] += p * vv.y;
                    accv[d4 + 2] += p * vv.z;
                    accv[d4 + 3] += p * vv.w;
                }
            }
            mrun = mnew;
        }
        __syncthreads();
    }

    const float inv = 1.f / lrun;
    __nv_bfloat162* oh = (__nv_bfloat162*)(g_ath + ((size_t)b * Sdim + q) * Cdim + h * HD);
    __nv_bfloat162* ol = (__nv_bfloat162*)(g_atl + ((size_t)b * Sdim + q) * Cdim + h * HD);
#pragma unroll
    for (int d = 0; d < 64; d += 2) {
        const float v0 = accv[d] * inv;
        const float v1 = accv[d + 1] * inv;
        const __nv_bfloat16 h0 = __float2bfloat16(v0);
        const __nv_bfloat16 h1 = __float2bfloat16(v1);
        oh[d >> 1] = __nv_bfloat162(h0, h1);
        ol[d >> 1] = __nv_bfloat162(__float2bfloat16(v0 - __bfloat162float(h0)),
                                    __float2bfloat16(v1 - __bfloat162float(h1)));
    }
}

// ---------------------------------------------------------------------------
extern "C" void kernel_launch(void* const* d_in, const int* in_sizes, int n_in,
                              void* d_out, int out_size)
{
    const float* x     = (const float*)d_in[0];
    const float* y     = (const float*)d_in[1];
    const unsigned char* mask = (const unsigned char*)d_in[2];
    const float* Wq_b  = (const float*)d_in[4];
    const float* Wkv_b = (const float*)d_in[6];
    const float* Wo_b  = (const float*)d_in[8];
    float* out = (float*)d_out;

    // bf16 hi/lo splits (inputs from harness; destinations are device globals
    // selected inside the kernels)
    const int nx = Mrows * Cdim / 4;
    split_k<0><<<(nx + 255) / 256, 256>>>((const float4*)x, nx);
    split_k<1><<<(nx + 255) / 256, 256>>>((const float4*)y, nx);
    const int nq = Cdim * Cdim / 4;
    split_k<2><<<(nq + 255) / 256, 256>>>((const float4*)d_in[3], nq);   // Wq_w
    const int nkv = 2 * Cdim * Cdim / 4;
    split_k<3><<<(nkv + 255) / 256, 256>>>((const float4*)d_in[5], nkv); // Wkv_w
    split_k<4><<<(nq + 255) / 256, 256>>>((const float4*)d_in[7], nq);   // Wo_w

    // Q projection -> g_q [b,h,s,d]
    gemm_tc<0><<<dim3(Cdim / 128, Mrows / 128), 256>>>(Wq_b, nullptr);
    // KV projection -> g_k / g_v
    gemm_tc<1><<<dim3(2 * Cdim / 128, Mrows / 128), 256>>>(Wkv_b, nullptr);
    // Attention -> g_ath/g_atl (bf16 hi/lo, row-major [m][c])
    attn_k<<<dim3(Sdim / 128, NH, Bdim), 128>>>(mask);
    // O projection -> out
    gemm_tc<2><<<dim3(Cdim / 128, Mrows / 128), 256>>>(Wo_b, out);
}

// round 6
// speedup vs baseline: 2.4485x; 1.8935x over previous
#include <cuda_runtime.h>
#include <cuda_bf16.h>
#include <cstdint>

// Problem constants
#define Bdim 4
#define Sdim 2048
#define Cdim 1024
#define NH   16
#define HD   64
#define Mrows (Bdim * Sdim)   // 8192

// ---------------------------------------------------------------------------
// Scratch (__device__ globals; referenced ONLY from device code)
// ---------------------------------------------------------------------------
__device__ __align__(16) __nv_bfloat16 g_qh[Bdim * NH * Sdim * HD];
__device__ __align__(16) __nv_bfloat16 g_ql[Bdim * NH * Sdim * HD];
__device__ __align__(16) __nv_bfloat16 g_kh[Bdim * NH * Sdim * HD];
__device__ __align__(16) __nv_bfloat16 g_kl[Bdim * NH * Sdim * HD];
__device__ __align__(16) __nv_bfloat16 g_vh[Bdim * NH * Sdim * HD];
__device__ __align__(16) __nv_bfloat16 g_vl[Bdim * NH * Sdim * HD];

__device__ __align__(16) __nv_bfloat16 g_xh[Mrows * Cdim];
__device__ __align__(16) __nv_bfloat16 g_xl[Mrows * Cdim];
__device__ __align__(16) __nv_bfloat16 g_yh[Mrows * Cdim];
__device__ __align__(16) __nv_bfloat16 g_yl[Mrows * Cdim];
__device__ __align__(16) __nv_bfloat16 g_ath[Mrows * Cdim];
__device__ __align__(16) __nv_bfloat16 g_atl[Mrows * Cdim];
__device__ __align__(16) __nv_bfloat16 g_wqh[Cdim * Cdim];
__device__ __align__(16) __nv_bfloat16 g_wql[Cdim * Cdim];
__device__ __align__(16) __nv_bfloat16 g_wkvh[2 * Cdim * Cdim];
__device__ __align__(16) __nv_bfloat16 g_wkvl[2 * Cdim * Cdim];
__device__ __align__(16) __nv_bfloat16 g_woh[Cdim * Cdim];
__device__ __align__(16) __nv_bfloat16 g_wol[Cdim * Cdim];

// ---------------------------------------------------------------------------
// PTX helpers (base sm_103 ISA: cp.async, ldmatrix, mma.sync)
// ---------------------------------------------------------------------------
__device__ __forceinline__ uint32_t smem_u32(const void* p) {
    uint32_t a;
    asm("{ .reg .u64 t; cvta.to.shared.u64 t, %1; cvt.u32.u64 %0, t; }"
        : "=r"(a) : "l"(p));
    return a;
}

#define CP_ASYNC16(sa, ga) \
    asm volatile("cp.async.cg.shared.global [%0], [%1], 16;" :: "r"(sa), "l"(ga) : "memory")
#define CP_COMMIT() asm volatile("cp.async.commit_group;" ::: "memory")
#define CP_WAIT(n)  asm volatile("cp.async.wait_group %0;" :: "n"(n) : "memory")

__device__ __forceinline__ void ldsm_x4(uint32_t* r, uint32_t addr) {
    asm volatile("ldmatrix.sync.aligned.m8n8.x4.shared.b16 {%0,%1,%2,%3}, [%4];"
                 : "=r"(r[0]), "=r"(r[1]), "=r"(r[2]), "=r"(r[3]) : "r"(addr));
}
__device__ __forceinline__ void ldsm_x4t(uint32_t* r, uint32_t addr) {
    asm volatile("ldmatrix.sync.aligned.m8n8.x4.trans.shared.b16 {%0,%1,%2,%3}, [%4];"
                 : "=r"(r[0]), "=r"(r[1]), "=r"(r[2]), "=r"(r[3]) : "r"(addr));
}
__device__ __forceinline__ void mma_bf16(float* d, const uint32_t* a, const uint32_t* b) {
    asm volatile("mma.sync.aligned.m16n8k16.row.col.f32.bf16.bf16.f32 "
                 "{%0,%1,%2,%3}, {%4,%5,%6,%7}, {%8,%9}, {%0,%1,%2,%3};"
                 : "+f"(d[0]), "+f"(d[1]), "+f"(d[2]), "+f"(d[3])
                 : "r"(a[0]), "r"(a[1]), "r"(a[2]), "r"(a[3]), "r"(b[0]), "r"(b[1]));
}

// pack two fp32 -> bf16x2 (lo in low half, hi in high half)
__device__ __forceinline__ uint32_t pack_bf16x2(float lo, float hi) {
    uint32_t r;
    asm("cvt.rn.bf16x2.f32 %0, %1, %2;" : "=r"(r) : "f"(hi), "f"(lo));
    return r;
}
// high-16-bit (truncated) pair pack: low half = v0's top bits, high = v1's
__device__ __forceinline__ uint32_t prmt_hi(float v0, float v1) {
    uint32_t r;
    asm("prmt.b32 %0, %1, %2, 0x7632;" : "=r"(r)
        : "r"(__float_as_uint(v0)), "r"(__float_as_uint(v1)));
    return r;
}
__device__ __forceinline__ float trunc_bf16(float v) {
    return __uint_as_float(__float_as_uint(v) & 0xFFFF0000u);
}

// polynomial exp (no MUFU) — valid for x <= ~0, clamped below -80
__device__ __forceinline__ float fast_exp(float x) {
    x = fmaxf(x, -80.f);
    const float y = x * 1.4426950408889634f;
    const float tt = y + 12582912.f;           // round-to-nearest-int magic
    const int   i  = __float_as_int(tt);       // low bits hold the integer
    const float n  = tt - 12582912.f;
    const float f  = y - n;                    // in [-0.5, 0.5]
    float p = 0.001333355815f;
    p = fmaf(p, f, 0.009618129842f);
    p = fmaf(p, f, 0.05550410866f);
    p = fmaf(p, f, 0.2402265069f);
    p = fmaf(p, f, 0.69314718056f);
    p = fmaf(p, f, 1.0f);
    return __int_as_float(__float_as_int(p) + (i << 23));
}

// ---------------------------------------------------------------------------
// fp32 -> bf16 hi/lo split. T selects destination.
// ---------------------------------------------------------------------------
template <int T>
__global__ __launch_bounds__(256)
void split_k(const float4* __restrict__ in, int n4)
{
    __nv_bfloat162* hi;
    __nv_bfloat162* lo;
    if (T == 0)      { hi = (__nv_bfloat162*)g_xh;  lo = (__nv_bfloat162*)g_xl;  }
    else if (T == 1) { hi = (__nv_bfloat162*)g_yh;  lo = (__nv_bfloat162*)g_yl;  }
    else if (T == 2) { hi = (__nv_bfloat162*)g_wqh; lo = (__nv_bfloat162*)g_wql; }
    else if (T == 3) { hi = (__nv_bfloat162*)g_wkvh;lo = (__nv_bfloat162*)g_wkvl;}
    else             { hi = (__nv_bfloat162*)g_woh; lo = (__nv_bfloat162*)g_wol; }

    const int i = blockIdx.x * 256 + threadIdx.x;
    if (i >= n4) return;
    const float4 v = in[i];
    const __nv_bfloat16 h0 = __float2bfloat16(v.x);
    const __nv_bfloat16 h1 = __float2bfloat16(v.y);
    const __nv_bfloat16 h2 = __float2bfloat16(v.z);
    const __nv_bfloat16 h3 = __float2bfloat16(v.w);
    hi[2 * i + 0] = __nv_bfloat162(h0, h1);
    hi[2 * i + 1] = __nv_bfloat162(h2, h3);
    lo[2 * i + 0] = __nv_bfloat162(__float2bfloat16(v.x - __bfloat162float(h0)),
                                   __float2bfloat16(v.y - __bfloat162float(h1)));
    lo[2 * i + 1] = __nv_bfloat162(__float2bfloat16(v.z - __bfloat162float(h2)),
                                   __float2bfloat16(v.w - __bfloat162float(h3)));
}

// ---------------------------------------------------------------------------
// HMMA GEMM (as R5) — epilogue now emits bf16 hi/lo Q/K/V for MODE 0/1.
// MODE 0: Q -> g_qh/g_ql [b,h,s,d], scaled by 0.125 (1/sqrt(HD), exact pow2)
// MODE 1: n<1024 -> g_kh/g_kl ; n>=1024 -> g_vh/g_vl
// MODE 2: fp32 out plain [m][n]
// ---------------------------------------------------------------------------
#define TILE_BYTES 4096u
#define BUF_BYTES  16384u
#define NSTAGE     64

template <int MODE>
__global__ __launch_bounds__(256)
void gemm_tc(const float* __restrict__ bias, float* __restrict__ out)
{
    const __nv_bfloat16 *Ah, *Al, *Bh, *Bl;
    if (MODE == 0)      { Ah = g_xh;  Al = g_xl;  Bh = g_wqh;  Bl = g_wql;  }
    else if (MODE == 1) { Ah = g_yh;  Al = g_yl;  Bh = g_wkvh; Bl = g_wkvl; }
    else                { Ah = g_ath; Al = g_atl; Bh = g_woh;  Bl = g_wol;  }

    __shared__ __align__(128) char smraw[2 * BUF_BYTES];
    const uint32_t smb = smem_u32(smraw);

    const int tid = threadIdx.x;
    const int wid = tid >> 5;
    const int lane = tid & 31;
    const int m0 = blockIdx.y * 128;
    const int n0 = blockIdx.x * 128;
    const int warp_m = (wid & 1) * 64;
    const int warp_n = (wid >> 1) * 32;

    float acc[4][4][4];
#pragma unroll
    for (int i = 0; i < 4; ++i)
#pragma unroll
        for (int j = 0; j < 4; ++j)
#pragma unroll
            for (int c = 0; c < 4; ++c) acc[i][j][c] = 0.f;

    const int lrow = tid >> 1;
    const int lch  = tid & 1;

    auto load_stage = [&](int s) {
        const int k0g = s * 16;
        const uint32_t bufb = smb + (uint32_t)(s & 1) * BUF_BYTES;
        const uint32_t sa0 = bufb + (uint32_t)(lch * 2048 + lrow * 16);
#pragma unroll
        for (int t = 0; t < 4; ++t) {
            const __nv_bfloat16* base = (t == 0) ? Ah : (t == 1) ? Al : (t == 2) ? Bh : Bl;
            const int r0 = (t < 2) ? m0 : n0;
            const __nv_bfloat16* g = base + (size_t)(r0 + lrow) * Cdim + k0g + lch * 8;
            CP_ASYNC16(sa0 + (uint32_t)t * TILE_BYTES, g);
        }
        CP_COMMIT();
    };

    load_stage(0);

    for (int s = 0; s < NSTAGE; ++s) {
        if (s + 1 < NSTAGE) { load_stage(s + 1); CP_WAIT(1); }
        else                { CP_WAIT(0); }
        __syncthreads();

        const uint32_t bufb = smb + (uint32_t)(s & 1) * BUF_BYTES;
        const uint32_t bAh = bufb + 0 * TILE_BYTES;
        const uint32_t bAl = bufb + 1 * TILE_BYTES;
        const uint32_t bBh = bufb + 2 * TILE_BYTES;
        const uint32_t bBl = bufb + 3 * TILE_BYTES;

        uint32_t af_h[4][4], af_l[4][4];
        {
            const int arow = warp_m + (lane & 15);
            const int kc = lane >> 4;
#pragma unroll
            for (int tm = 0; tm < 4; ++tm) {
                const uint32_t off = (uint32_t)(kc * 2048 + (arow + tm * 16) * 16);
                ldsm_x4(af_h[tm], bAh + off);
                ldsm_x4(af_l[tm], bAl + off);
            }
        }
        uint32_t bf_h[4][2], bf_l[4][2];
        {
            const int g = lane >> 3;
            const int nr = (lane & 7) + ((g >> 1) << 3);
            const int kc = g & 1;
#pragma unroll
            for (int half = 0; half < 2; ++half) {
                const int row = warp_n + half * 16 + nr;
                const uint32_t off = (uint32_t)(kc * 2048 + row * 16);
                uint32_t r4[4];
                ldsm_x4(r4, bBh + off);
                bf_h[half * 2 + 0][0] = r4[0]; bf_h[half * 2 + 0][1] = r4[1];
                bf_h[half * 2 + 1][0] = r4[2]; bf_h[half * 2 + 1][1] = r4[3];
                ldsm_x4(r4, bBl + off);
                bf_l[half * 2 + 0][0] = r4[0]; bf_l[half * 2 + 0][1] = r4[1];
                bf_l[half * 2 + 1][0] = r4[2]; bf_l[half * 2 + 1][1] = r4[3];
            }
        }

#pragma unroll
        for (int tm = 0; tm < 4; ++tm)
#pragma unroll
            for (int tn = 0; tn < 4; ++tn) {
                mma_bf16(acc[tm][tn], af_h[tm], bf_h[tn]);
                mma_bf16(acc[tm][tn], af_l[tm], bf_h[tn]);
                mma_bf16(acc[tm][tn], af_h[tm], bf_l[tn]);
            }

        __syncthreads();
    }

    // ---- epilogue
#pragma unroll
    for (int tm = 0; tm < 4; ++tm) {
#pragma unroll
        for (int tn = 0; tn < 4; ++tn) {
            const int rbase = m0 + warp_m + tm * 16 + (lane >> 2);
            const int c = n0 + warp_n + tn * 8 + (lane & 3) * 2;
            const float b0 = bias[c], b1 = bias[c + 1];
#pragma unroll
            for (int half = 0; half < 2; ++half) {
                const int m = rbase + half * 8;
                float v0 = acc[tm][tn][half * 2 + 0] + b0;
                float v1 = acc[tm][tn][half * 2 + 1] + b1;
                if (MODE == 2) {
                    float2 o; o.x = v0; o.y = v1;
                    *(float2*)(out + (size_t)m * Cdim + c) = o;
                } else {
                    if (MODE == 0) { v0 *= 0.125f; v1 *= 0.125f; }
                    const uint32_t hib = prmt_hi(v0, v1);
                    const uint32_t lob = pack_bf16x2(v0 - trunc_bf16(v0),
                                                     v1 - trunc_bf16(v1));
                    const int bb = m >> 11;
                    const int ss = m & (Sdim - 1);
                    __nv_bfloat16 *dh, *dl;
                    size_t idx;
                    if (MODE == 0) {
                        const int hh = c >> 6, dd = c & 63;
                        idx = (((size_t)bb * NH + hh) * Sdim + ss) * HD + dd;
                        dh = g_qh; dl = g_ql;
                    } else {
                        const int sel = c >> 10;
                        const int rr = c & 1023;
                        const int hh = rr >> 6, dd = rr & 63;
                        idx = (((size_t)bb * NH + hh) * Sdim + ss) * HD + dd;
                        dh = sel ? g_vh : g_kh; dl = sel ? g_vl : g_kl;
                    }
                    *(uint32_t*)(dh + idx) = hib;
                    *(uint32_t*)(dl + idx) = lob;
                }
            }
        }
    }
}

// ---------------------------------------------------------------------------
// Tensor-core flash attention.
// CTA = 64 queries (4 warps x 16 rows), key tiles of 64, causal tile skip.
// QK^T: 3-term bf16 split MMA; P*V: 3-term (P split by truncation).
// K/V staged via two 16KB single buffers, staggered cp.async pipeline.
// Output: bf16 hi/lo row-major [b*s][h*64+d] into g_ath/g_atl.
// ---------------------------------------------------------------------------
__global__ __launch_bounds__(128)
void attn_tc(const unsigned char* __restrict__ mask)
{
    __shared__ __align__(128) unsigned char kvraw[32768];
    __shared__ __align__(8) float maskadd[64];

    const int q0 = blockIdx.x * 64;
    const int h  = blockIdx.y;
    const int b  = blockIdx.z;
    const int tid = threadIdx.x;
    const int wid = tid >> 5;
    const int lane = tid & 31;
    const int g = lane >> 2, t = lane & 3;

    const uint32_t smb  = smem_u32(kvraw);
    const uint32_t kb_h = smb;
    const uint32_t kb_l = smb + 8192;
    const uint32_t vb_h = smb + 16384;
    const uint32_t vb_l = smb + 24576;

    const size_t bh = ((size_t)b * NH + h) * Sdim;
    const __nv_bfloat16* Qh = g_qh + (bh + q0) * HD;
    const __nv_bfloat16* Ql = g_ql + (bh + q0) * HD;
    const __nv_bfloat16* Kh = g_kh + bh * HD;
    const __nv_bfloat16* Kl = g_kl + bh * HD;
    const __nv_bfloat16* Vh = g_vh + bh * HD;
    const __nv_bfloat16* Vl = g_vl + bh * HD;

    // ---- stage Q through K buffer, load fragments to registers
#pragma unroll
    for (int i2 = 0; i2 < 4; ++i2) {
        const int e = i2 * 128 + tid;
        const int row = e >> 3, ch = e & 7;
        const uint32_t doff = (uint32_t)(ch * 1024 + row * 16);
        CP_ASYNC16(kb_h + doff, Qh + row * HD + ch * 8);
        CP_ASYNC16(kb_l + doff, Ql + row * HD + ch * 8);
    }
    CP_COMMIT(); CP_WAIT(0);
    __syncthreads();

    uint32_t qfh[4][4], qfl[4][4];
    {
        const int qrow = wid * 16 + (lane & 15);
#pragma unroll
        for (int ks = 0; ks < 4; ++ks) {
            const uint32_t a = (uint32_t)((2 * ks + (lane >> 4)) * 1024 + qrow * 16);
            ldsm_x4(qfh[ks], kb_h + a);
            ldsm_x4(qfl[ks], kb_l + a);
        }
    }
    __syncthreads();

    float oacc[8][4];
#pragma unroll
    for (int j = 0; j < 8; ++j)
#pragma unroll
        for (int c = 0; c < 4; ++c) oacc[j][c] = 0.f;
    float m0 = -1e30f, m1 = -1e30f, l0 = 0.f, l1 = 0.f;

    const unsigned char* mrow = mask + (size_t)b * Sdim;
    const int nt = blockIdx.x + 1;
    const int qg = q0 + wid * 16 + g;

    auto load_k = [&](int k0) {
#pragma unroll
        for (int i2 = 0; i2 < 4; ++i2) {
            const int e = i2 * 128 + tid;
            const int row = e >> 3, ch = e & 7;
            const uint32_t doff = (uint32_t)(ch * 1024 + row * 16);
            CP_ASYNC16(kb_h + doff, Kh + (size_t)(k0 + row) * HD + ch * 8);
            CP_ASYNC16(kb_l + doff, Kl + (size_t)(k0 + row) * HD + ch * 8);
        }
        CP_COMMIT();
    };
    auto load_v = [&](int k0) {
#pragma unroll
        for (int i2 = 0; i2 < 4; ++i2) {
            const int e = i2 * 128 + tid;
            const int row = e >> 3, ch = e & 7;
            const uint32_t doff = (uint32_t)(ch * 1024 + row * 16);
            CP_ASYNC16(vb_h + doff, Vh + (size_t)(k0 + row) * HD + ch * 8);
            CP_ASYNC16(vb_l + doff, Vl + (size_t)(k0 + row) * HD + ch * 8);
        }
        CP_COMMIT();
    };

    load_k(0);

    for (int it = 0; it < nt; ++it) {
        const int k0 = it * 64;

        CP_WAIT(0);                      // K_it resident
        if (tid < 64)
            maskadd[tid] = mrow[k0 + tid] ? -1e30f : 0.f;
        __syncthreads();                 // K visible, maskadd ready, V buf free
        load_v(k0);                      // V_it loads under S compute

        // ---- S = Q K^T (3-term)
        float sacc[8][4];
#pragma unroll
        for (int j = 0; j < 8; ++j)
#pragma unroll
            for (int c = 0; c < 4; ++c) sacc[j][c] = 0.f;

#pragma unroll
        for (int ks = 0; ks < 4; ++ks) {
            uint32_t kfh[8][2], kfl[8][2];
#pragma unroll
            for (int grp = 0; grp < 4; ++grp) {
                const uint32_t a = (uint32_t)((2 * ks + (lane >> 4)) * 1024 +
                                              (grp * 16 + (lane & 15)) * 16);
                uint32_t r[4];
                ldsm_x4(r, kb_h + a);
                kfh[2*grp][0] = r[0]; kfh[2*grp][1] = r[2];
                kfh[2*grp+1][0] = r[1]; kfh[2*grp+1][1] = r[3];
                ldsm_x4(r, kb_l + a);
                kfl[2*grp][0] = r[0]; kfl[2*grp][1] = r[2];
                kfl[2*grp+1][0] = r[1]; kfl[2*grp+1][1] = r[3];
            }
#pragma unroll
            for (int j = 0; j < 8; ++j) {
                mma_bf16(sacc[j], qfh[ks], kfh[j]);
                mma_bf16(sacc[j], qfl[ks], kfh[j]);
                mma_bf16(sacc[j], qfh[ks], kfl[j]);
            }
        }

        // ---- softmax (online)
        const bool diag = (k0 == q0);
        float mx0 = -1e30f, mx1 = -1e30f;
#pragma unroll
        for (int j = 0; j < 8; ++j) {
            const float2 ma = *(const float2*)&maskadd[8 * j + 2 * t];
            float s0 = sacc[j][0] + ma.x;
            float s1 = sacc[j][1] + ma.y;
            float s2 = sacc[j][2] + ma.x;
            float s3 = sacc[j][3] + ma.y;
            if (diag) {
                const int key = k0 + 8 * j + 2 * t;
                if (key     > qg)     s0 = -1e30f;
                if (key + 1 > qg)     s1 = -1e30f;
                if (key     > qg + 8) s2 = -1e30f;
                if (key + 1 > qg + 8) s3 = -1e30f;
            }
            sacc[j][0] = s0; sacc[j][1] = s1; sacc[j][2] = s2; sacc[j][3] = s3;
            mx0 = fmaxf(mx0, fmaxf(s0, s1));
            mx1 = fmaxf(mx1, fmaxf(s2, s3));
        }
        mx0 = fmaxf(mx0, __shfl_xor_sync(0xFFFFFFFFu, mx0, 1));
        mx0 = fmaxf(mx0, __shfl_xor_sync(0xFFFFFFFFu, mx0, 2));
        mx1 = fmaxf(mx1, __shfl_xor_sync(0xFFFFFFFFu, mx1, 1));
        mx1 = fmaxf(mx1, __shfl_xor_sync(0xFFFFFFFFu, mx1, 2));
        const float mn0 = fmaxf(m0, mx0), mn1 = fmaxf(m1, mx1);
        const float cr0 = fast_exp(m0 - mn0), cr1 = fast_exp(m1 - mn1);
        m0 = mn0; m1 = mn1;
        l0 *= cr0; l1 *= cr1;
#pragma unroll
        for (int j = 0; j < 8; ++j) {
            oacc[j][0] *= cr0; oacc[j][1] *= cr0;
            oacc[j][2] *= cr1; oacc[j][3] *= cr1;
        }

        float sum0 = 0.f, sum1 = 0.f;
        uint32_t pfh[4][4], pfl[4][4];
#pragma unroll
        for (int j = 0; j < 8; ++j) {
            const float p0 = fast_exp(sacc[j][0] - mn0);
            const float p1 = fast_exp(sacc[j][1] - mn0);
            const float p2 = fast_exp(sacc[j][2] - mn1);
            const float p3 = fast_exp(sacc[j][3] - mn1);
            sum0 += p0 + p1; sum1 += p2 + p3;
            const uint32_t hi01 = prmt_hi(p0, p1);
            const uint32_t hi23 = prmt_hi(p2, p3);
            const uint32_t lo01 = pack_bf16x2(p0 - trunc_bf16(p0), p1 - trunc_bf16(p1));
            const uint32_t lo23 = pack_bf16x2(p2 - trunc_bf16(p2), p3 - trunc_bf16(p3));
            const int kk = j >> 1, sl = (j & 1) * 2;
            pfh[kk][sl + 0] = hi01; pfh[kk][sl + 1] = hi23;
            pfl[kk][sl + 0] = lo01; pfl[kk][sl + 1] = lo23;
        }
        sum0 += __shfl_xor_sync(0xFFFFFFFFu, sum0, 1);
        sum0 += __shfl_xor_sync(0xFFFFFFFFu, sum0, 2);
        sum1 += __shfl_xor_sync(0xFFFFFFFFu, sum1, 1);
        sum1 += __shfl_xor_sync(0xFFFFFFFFu, sum1, 2);
        l0 += sum0; l1 += sum1;

        CP_WAIT(0);                      // V_it resident
        __syncthreads();                 // V visible, K buf free (all warps past S)
        if (it + 1 < nt) load_k(k0 + 64);

        // ---- O += P V (3-term)
#pragma unroll
        for (int kp = 0; kp < 4; ++kp) {
            uint32_t vfh[8][2], vfl[8][2];
#pragma unroll
            for (int db = 0; db < 4; ++db) {
                const uint32_t a = (uint32_t)((2 * db + (lane >> 4)) * 1024 +
                                              (kp * 16 + (lane & 15)) * 16);
                uint32_t r[4];
                ldsm_x4t(r, vb_h + a);
                vfh[2*db][0] = r[0]; vfh[2*db][1] = r[1];
                vfh[2*db+1][0] = r[2]; vfh[2*db+1][1] = r[3];
                ldsm_x4t(r, vb_l + a);
                vfl[2*db][0] = r[0]; vfl[2*db][1] = r[1];
                vfl[2*db+1][0] = r[2]; vfl[2*db+1][1] = r[3];
            }
#pragma unroll
            for (int j = 0; j < 8; ++j) {
                mma_bf16(oacc[j], pfh[kp], vfh[j]);
                mma_bf16(oacc[j], pfl[kp], vfh[j]);
                mma_bf16(oacc[j], pfh[kp], vfl[j]);
            }
        }
    }

    // ---- epilogue: o/l -> bf16 hi/lo at [b*s + q][h*64 + d]
    const float inv0 = 1.f / l0;
    const float inv1 = 1.f / l1;
    __nv_bfloat16* oh0 = g_ath + ((size_t)b * Sdim + qg) * Cdim + h * HD;
    __nv_bfloat16* ol0 = g_atl + ((size_t)b * Sdim + qg) * Cdim + h * HD;
    __nv_bfloat16* oh1 = oh0 + 8 * Cdim;
    __nv_bfloat16* ol1 = ol0 + 8 * Cdim;
#pragma unroll
    for (int j = 0; j < 8; ++j) {
        const int d = 8 * j + 2 * t;
        const float o0 = oacc[j][0] * inv0, o1 = oacc[j][1] * inv0;
        const float o2 = oacc[j][2] * inv1, o3 = oacc[j][3] * inv1;
        *(uint32_t*)(oh0 + d) = prmt_hi(o0, o1);
        *(uint32_t*)(ol0 + d) = pack_bf16x2(o0 - trunc_bf16(o0), o1 - trunc_bf16(o1));
        *(uint32_t*)(oh1 + d) = prmt_hi(o2, o3);
        *(uint32_t*)(ol1 + d) = pack_bf16x2(o2 - trunc_bf16(o2), o3 - trunc_bf16(o3));
    }
}

// ---------------------------------------------------------------------------
extern "C" void kernel_launch(void* const* d_in, const int* in_sizes, int n_in,
                              void* d_out, int out_size)
{
    const float* x     = (const float*)d_in[0];
    const float* y     = (const float*)d_in[1];
    const unsigned char* mask = (const unsigned char*)d_in[2];
    const float* Wq_b  = (const float*)d_in[4];
    const float* Wkv_b = (const float*)d_in[6];
    const float* Wo_b  = (const float*)d_in[8];
    float* out = (float*)d_out;

    const int nx = Mrows * Cdim / 4;
    split_k<0><<<(nx + 255) / 256, 256>>>((const float4*)x, nx);
    split_k<1><<<(nx + 255) / 256, 256>>>((const float4*)y, nx);
    const int nq = Cdim * Cdim / 4;
    split_k<2><<<(nq + 255) / 256, 256>>>((const float4*)d_in[3], nq);   // Wq_w
    const int nkv = 2 * Cdim * Cdim / 4;
    split_k<3><<<(nkv + 255) / 256, 256>>>((const float4*)d_in[5], nkv); // Wkv_w
    split_k<4><<<(nq + 255) / 256, 256>>>((const float4*)d_in[7], nq);   // Wo_w

    // Q projection -> g_qh/g_ql (pre-scaled by 1/8)
    gemm_tc<0><<<dim3(Cdim / 128, Mrows / 128), 256>>>(Wq_b, nullptr);
    // KV projection -> g_kh/g_kl, g_vh/g_vl
    gemm_tc<1><<<dim3(2 * Cdim / 128, Mrows / 128), 256>>>(Wkv_b, nullptr);
    // Tensor-core flash attention -> g_ath/g_atl
    attn_tc<<<dim3(Sdim / 64, NH, Bdim), 128>>>(mask);
    // O projection -> out
    gemm_tc<2><<<dim3(Cdim / 128, Mrows / 128), 256>>>(Wo_b, out);
}

// round 7
// speedup vs baseline: 2.5306x; 1.0335x over previous
#include <cuda_runtime.h>
#include <cuda_bf16.h>
#include <cstdint>

// Problem constants
#define Bdim 4
#define Sdim 2048
#define Cdim 1024
#define NH   16
#define HD   64
#define Mrows (Bdim * Sdim)   // 8192

// ---------------------------------------------------------------------------
// Scratch (__device__ globals; referenced ONLY from device code)
// ---------------------------------------------------------------------------
__device__ __align__(16) __nv_bfloat16 g_qh[Bdim * NH * Sdim * HD];
__device__ __align__(16) __nv_bfloat16 g_ql[Bdim * NH * Sdim * HD];
__device__ __align__(16) __nv_bfloat16 g_kh[Bdim * NH * Sdim * HD];
__device__ __align__(16) __nv_bfloat16 g_kl[Bdim * NH * Sdim * HD];
__device__ __align__(16) __nv_bfloat16 g_vh[Bdim * NH * Sdim * HD];
__device__ __align__(16) __nv_bfloat16 g_vl[Bdim * NH * Sdim * HD];

__device__ __align__(16) __nv_bfloat16 g_xh[Mrows * Cdim];
__device__ __align__(16) __nv_bfloat16 g_xl[Mrows * Cdim];
__device__ __align__(16) __nv_bfloat16 g_yh[Mrows * Cdim];
__device__ __align__(16) __nv_bfloat16 g_yl[Mrows * Cdim];
__device__ __align__(16) __nv_bfloat16 g_ath[Mrows * Cdim];
__device__ __align__(16) __nv_bfloat16 g_atl[Mrows * Cdim];
__device__ __align__(16) __nv_bfloat16 g_wqh[Cdim * Cdim];
__device__ __align__(16) __nv_bfloat16 g_wql[Cdim * Cdim];
__device__ __align__(16) __nv_bfloat16 g_wkvh[2 * Cdim * Cdim];
__device__ __align__(16) __nv_bfloat16 g_wkvl[2 * Cdim * Cdim];
__device__ __align__(16) __nv_bfloat16 g_woh[Cdim * Cdim];
__device__ __align__(16) __nv_bfloat16 g_wol[Cdim * Cdim];

// ---------------------------------------------------------------------------
// PTX helpers (base sm_103 ISA: cp.async, ldmatrix, mma.sync)
// ---------------------------------------------------------------------------
__device__ __forceinline__ uint32_t smem_u32(const void* p) {
    uint32_t a;
    asm("{ .reg .u64 t; cvta.to.shared.u64 t, %1; cvt.u32.u64 %0, t; }"
        : "=r"(a) : "l"(p));
    return a;
}

#define CP_ASYNC16(sa, ga) \
    asm volatile("cp.async.cg.shared.global [%0], [%1], 16;" :: "r"(sa), "l"(ga) : "memory")
#define CP_COMMIT() asm volatile("cp.async.commit_group;" ::: "memory")
#define CP_WAIT(n)  asm volatile("cp.async.wait_group %0;" :: "n"(n) : "memory")

__device__ __forceinline__ void ldsm_x4(uint32_t* r, uint32_t addr) {
    asm volatile("ldmatrix.sync.aligned.m8n8.x4.shared.b16 {%0,%1,%2,%3}, [%4];"
                 : "=r"(r[0]), "=r"(r[1]), "=r"(r[2]), "=r"(r[3]) : "r"(addr));
}
__device__ __forceinline__ void ldsm_x4t(uint32_t* r, uint32_t addr) {
    asm volatile("ldmatrix.sync.aligned.m8n8.x4.trans.shared.b16 {%0,%1,%2,%3}, [%4];"
                 : "=r"(r[0]), "=r"(r[1]), "=r"(r[2]), "=r"(r[3]) : "r"(addr));
}
__device__ __forceinline__ void mma_bf16(float* d, const uint32_t* a, const uint32_t* b) {
    asm volatile("mma.sync.aligned.m16n8k16.row.col.f32.bf16.bf16.f32 "
                 "{%0,%1,%2,%3}, {%4,%5,%6,%7}, {%8,%9}, {%0,%1,%2,%3};"
                 : "+f"(d[0]), "+f"(d[1]), "+f"(d[2]), "+f"(d[3])
                 : "r"(a[0]), "r"(a[1]), "r"(a[2]), "r"(a[3]), "r"(b[0]), "r"(b[1]));
}

__device__ __forceinline__ uint32_t pack_bf16x2(float lo, float hi) {
    uint32_t r;
    asm("cvt.rn.bf16x2.f32 %0, %1, %2;" : "=r"(r) : "f"(hi), "f"(lo));
    return r;
}
__device__ __forceinline__ uint32_t prmt_hi(float v0, float v1) {
    uint32_t r;
    asm("prmt.b32 %0, %1, %2, 0x7632;" : "=r"(r)
        : "r"(__float_as_uint(v0)), "r"(__float_as_uint(v1)));
    return r;
}
__device__ __forceinline__ float trunc_bf16(float v) {
    return __uint_as_float(__float_as_uint(v) & 0xFFFF0000u);
}

// polynomial exp (no MUFU) — valid for x <= ~0, clamped below -80
__device__ __forceinline__ float fast_exp(float x) {
    x = fmaxf(x, -80.f);
    const float y = x * 1.4426950408889634f;
    const float tt = y + 12582912.f;
    const int   i  = __float_as_int(tt);
    const float n  = tt - 12582912.f;
    const float f  = y - n;
    float p = 0.001333355815f;
    p = fmaf(p, f, 0.009618129842f);
    p = fmaf(p, f, 0.05550410866f);
    p = fmaf(p, f, 0.2402265069f);
    p = fmaf(p, f, 0.69314718056f);
    p = fmaf(p, f, 1.0f);
    return __int_as_float(__float_as_int(p) + (i << 23));
}

// ---------------------------------------------------------------------------
// fp32 -> bf16 hi/lo split. T selects destination.
// ---------------------------------------------------------------------------
template <int T>
__global__ __launch_bounds__(256)
void split_k(const float4* __restrict__ in, int n4)
{
    __nv_bfloat162* hi;
    __nv_bfloat162* lo;
    if (T == 0)      { hi = (__nv_bfloat162*)g_xh;  lo = (__nv_bfloat162*)g_xl;  }
    else if (T == 1) { hi = (__nv_bfloat162*)g_yh;  lo = (__nv_bfloat162*)g_yl;  }
    else if (T == 2) { hi = (__nv_bfloat162*)g_wqh; lo = (__nv_bfloat162*)g_wql; }
    else if (T == 3) { hi = (__nv_bfloat162*)g_wkvh;lo = (__nv_bfloat162*)g_wkvl;}
    else             { hi = (__nv_bfloat162*)g_woh; lo = (__nv_bfloat162*)g_wol; }

    const int i = blockIdx.x * 256 + threadIdx.x;
    if (i >= n4) return;
    const float4 v = in[i];
    const __nv_bfloat16 h0 = __float2bfloat16(v.x);
    const __nv_bfloat16 h1 = __float2bfloat16(v.y);
    const __nv_bfloat16 h2 = __float2bfloat16(v.z);
    const __nv_bfloat16 h3 = __float2bfloat16(v.w);
    hi[2 * i + 0] = __nv_bfloat162(h0, h1);
    hi[2 * i + 1] = __nv_bfloat162(h2, h3);
    lo[2 * i + 0] = __nv_bfloat162(__float2bfloat16(v.x - __bfloat162float(h0)),
                                   __float2bfloat16(v.y - __bfloat162float(h1)));
    lo[2 * i + 1] = __nv_bfloat162(__float2bfloat16(v.z - __bfloat162float(h2)),
                                   __float2bfloat16(v.w - __bfloat162float(h3)));
}

// ---------------------------------------------------------------------------
// HMMA GEMM, 3-stage cp.async pipeline, one barrier per K-stage.
// MODE 0: Q -> g_qh/g_ql (scaled 0.125); MODE 1: K/V hi/lo; MODE 2: fp32 out.
// ---------------------------------------------------------------------------
#define TILE_BYTES 4096u
#define BUF_BYTES  16384u
#define NSTAGE     64

template <int MODE>
__global__ __launch_bounds__(256)
void gemm_tc(const float* __restrict__ bias, float* __restrict__ out)
{
    const __nv_bfloat16 *Ah, *Al, *Bh, *Bl;
    if (MODE == 0)      { Ah = g_xh;  Al = g_xl;  Bh = g_wqh;  Bl = g_wql;  }
    else if (MODE == 1) { Ah = g_yh;  Al = g_yl;  Bh = g_wkvh; Bl = g_wkvl; }
    else                { Ah = g_ath; Al = g_atl; Bh = g_woh;  Bl = g_wol;  }

    __shared__ __align__(128) char smraw[3 * BUF_BYTES];   // 48 KB static
    const uint32_t smb = smem_u32(smraw);

    const int tid = threadIdx.x;
    const int wid = tid >> 5;
    const int lane = tid & 31;
    const int m0 = blockIdx.y * 128;
    const int n0 = blockIdx.x * 128;
    const int warp_m = (wid & 1) * 64;
    const int warp_n = (wid >> 1) * 32;

    float acc[4][4][4];
#pragma unroll
    for (int i = 0; i < 4; ++i)
#pragma unroll
        for (int j = 0; j < 4; ++j)
#pragma unroll
            for (int c = 0; c < 4; ++c) acc[i][j][c] = 0.f;

    const int lrow = tid >> 1;
    const int lch  = tid & 1;

    auto load_stage = [&](int s) {
        const int k0g = s * 16;
        const uint32_t bufb = smb + (uint32_t)(s % 3) * BUF_BYTES;
        const uint32_t sa0 = bufb + (uint32_t)(lch * 2048 + lrow * 16);
#pragma unroll
        for (int t = 0; t < 4; ++t) {
            const __nv_bfloat16* base = (t == 0) ? Ah : (t == 1) ? Al : (t == 2) ? Bh : Bl;
            const int r0 = (t < 2) ? m0 : n0;
            const __nv_bfloat16* g = base + (size_t)(r0 + lrow) * Cdim + k0g + lch * 8;
            CP_ASYNC16(sa0 + (uint32_t)t * TILE_BYTES, g);
        }
        CP_COMMIT();
    };

    load_stage(0);
    load_stage(1);

    for (int s = 0; s < NSTAGE; ++s) {
        // stage s resident: committed groups 0..min(s+1,N-1); allow 1 pending
        if (s < NSTAGE - 1) { CP_WAIT(1); }
        else                { CP_WAIT(0); }
        __syncthreads();                 // also frees buffer (s+2)%3 for prefetch
        if (s + 2 < NSTAGE) load_stage(s + 2);

        const uint32_t bufb = smb + (uint32_t)(s % 3) * BUF_BYTES;
        const uint32_t bAh = bufb + 0 * TILE_BYTES;
        const uint32_t bAl = bufb + 1 * TILE_BYTES;
        const uint32_t bBh = bufb + 2 * TILE_BYTES;
        const uint32_t bBl = bufb + 3 * TILE_BYTES;

        uint32_t af_h[4][4], af_l[4][4];
        {
            const int arow = warp_m + (lane & 15);
            const int kc = lane >> 4;
#pragma unroll
            for (int tm = 0; tm < 4; ++tm) {
                const uint32_t off = (uint32_t)(kc * 2048 + (arow + tm * 16) * 16);
                ldsm_x4(af_h[tm], bAh + off);
                ldsm_x4(af_l[tm], bAl + off);
            }
        }
        uint32_t bf_h[4][2], bf_l[4][2];
        {
            const int g = lane >> 3;
            const int nr = (lane & 7) + ((g >> 1) << 3);
            const int kc = g & 1;
#pragma unroll
            for (int half = 0; half < 2; ++half) {
                const int row = warp_n + half * 16 + nr;
                const uint32_t off = (uint32_t)(kc * 2048 + row * 16);
                uint32_t r4[4];
                ldsm_x4(r4, bBh + off);
                bf_h[half * 2 + 0][0] = r4[0]; bf_h[half * 2 + 0][1] = r4[1];
                bf_h[half * 2 + 1][0] = r4[2]; bf_h[half * 2 + 1][1] = r4[3];
                ldsm_x4(r4, bBl + off);
                bf_l[half * 2 + 0][0] = r4[0]; bf_l[half * 2 + 0][1] = r4[1];
                bf_l[half * 2 + 1][0] = r4[2]; bf_l[half * 2 + 1][1] = r4[3];
            }
        }

        // term-outermost: consecutive MMAs hit 16 independent accumulators
#pragma unroll
        for (int tm = 0; tm < 4; ++tm)
#pragma unroll
            for (int tn = 0; tn < 4; ++tn)
                mma_bf16(acc[tm][tn], af_h[tm], bf_h[tn]);
#pragma unroll
        for (int tm = 0; tm < 4; ++tm)
#pragma unroll
            for (int tn = 0; tn < 4; ++tn)
                mma_bf16(acc[tm][tn], af_l[tm], bf_h[tn]);
#pragma unroll
        for (int tm = 0; tm < 4; ++tm)
#pragma unroll
            for (int tn = 0; tn < 4; ++tn)
                mma_bf16(acc[tm][tn], af_h[tm], bf_l[tn]);
    }

    // ---- epilogue
#pragma unroll
    for (int tm = 0; tm < 4; ++tm) {
#pragma unroll
        for (int tn = 0; tn < 4; ++tn) {
            const int rbase = m0 + warp_m + tm * 16 + (lane >> 2);
            const int c = n0 + warp_n + tn * 8 + (lane & 3) * 2;
            const float b0 = bias[c], b1 = bias[c + 1];
#pragma unroll
            for (int half = 0; half < 2; ++half) {
                const int m = rbase + half * 8;
                float v0 = acc[tm][tn][half * 2 + 0] + b0;
                float v1 = acc[tm][tn][half * 2 + 1] + b1;
                if (MODE == 2) {
                    float2 o; o.x = v0; o.y = v1;
                    *(float2*)(out + (size_t)m * Cdim + c) = o;
                } else {
                    if (MODE == 0) { v0 *= 0.125f; v1 *= 0.125f; }
                    const uint32_t hib = prmt_hi(v0, v1);
                    const uint32_t lob = pack_bf16x2(v0 - trunc_bf16(v0),
                                                     v1 - trunc_bf16(v1));
                    const int bb = m >> 11;
                    const int ss = m & (Sdim - 1);
                    __nv_bfloat16 *dh, *dl;
                    size_t idx;
                    if (MODE == 0) {
                        const int hh = c >> 6, dd = c & 63;
                        idx = (((size_t)bb * NH + hh) * Sdim + ss) * HD + dd;
                        dh = g_qh; dl = g_ql;
                    } else {
                        const int sel = c >> 10;
                        const int rr = c & 1023;
                        const int hh = rr >> 6, dd = rr & 63;
                        idx = (((size_t)bb * NH + hh) * Sdim + ss) * HD + dd;
                        dh = sel ? g_vh : g_kh; dl = sel ? g_vl : g_kl;
                    }
                    *(uint32_t*)(dh + idx) = hib;
                    *(uint32_t*)(dl + idx) = lob;
                }
            }
        }
    }
}

// ---------------------------------------------------------------------------
// Tensor-core flash attention (64q CTA, 64-key tiles, staggered K/V pipeline).
// MMA loops term-outermost for independent accumulator chains.
// ---------------------------------------------------------------------------
__global__ __launch_bounds__(128)
void attn_tc(const unsigned char* __restrict__ mask)
{
    __shared__ __align__(128) unsigned char kvraw[32768];
    __shared__ __align__(8) float maskadd[64];

    const int q0 = blockIdx.x * 64;
    const int h  = blockIdx.y;
    const int b  = blockIdx.z;
    const int tid = threadIdx.x;
    const int wid = tid >> 5;
    const int lane = tid & 31;
    const int g = lane >> 2, t = lane & 3;

    const uint32_t smb  = smem_u32(kvraw);
    const uint32_t kb_h = smb;
    const uint32_t kb_l = smb + 8192;
    const uint32_t vb_h = smb + 16384;
    const uint32_t vb_l = smb + 24576;

    const size_t bh = ((size_t)b * NH + h) * Sdim;
    const __nv_bfloat16* Qh = g_qh + (bh + q0) * HD;
    const __nv_bfloat16* Ql = g_ql + (bh + q0) * HD;
    const __nv_bfloat16* Kh = g_kh + bh * HD;
    const __nv_bfloat16* Kl = g_kl + bh * HD;
    const __nv_bfloat16* Vh = g_vh + bh * HD;
    const __nv_bfloat16* Vl = g_vl + bh * HD;

#pragma unroll
    for (int i2 = 0; i2 < 4; ++i2) {
        const int e = i2 * 128 + tid;
        const int row = e >> 3, ch = e & 7;
        const uint32_t doff = (uint32_t)(ch * 1024 + row * 16);
        CP_ASYNC16(kb_h + doff, Qh + row * HD + ch * 8);
        CP_ASYNC16(kb_l + doff, Ql + row * HD + ch * 8);
    }
    CP_COMMIT(); CP_WAIT(0);
    __syncthreads();

    uint32_t qfh[4][4], qfl[4][4];
    {
        const int qrow = wid * 16 + (lane & 15);
#pragma unroll
        for (int ks = 0; ks < 4; ++ks) {
            const uint32_t a = (uint32_t)((2 * ks + (lane >> 4)) * 1024 + qrow * 16);
            ldsm_x4(qfh[ks], kb_h + a);
            ldsm_x4(qfl[ks], kb_l + a);
        }
    }
    __syncthreads();

    float oacc[8][4];
#pragma unroll
    for (int j = 0; j < 8; ++j)
#pragma unroll
        for (int c = 0; c < 4; ++c) oacc[j][c] = 0.f;
    float m0 = -1e30f, m1 = -1e30f, l0 = 0.f, l1 = 0.f;

    const unsigned char* mrow = mask + (size_t)b * Sdim;
    const int nt = blockIdx.x + 1;
    const int qg = q0 + wid * 16 + g;

    auto load_k = [&](int k0) {
#pragma unroll
        for (int i2 = 0; i2 < 4; ++i2) {
            const int e = i2 * 128 + tid;
            const int row = e >> 3, ch = e & 7;
            const uint32_t doff = (uint32_t)(ch * 1024 + row * 16);
            CP_ASYNC16(kb_h + doff, Kh + (size_t)(k0 + row) * HD + ch * 8);
            CP_ASYNC16(kb_l + doff, Kl + (size_t)(k0 + row) * HD + ch * 8);
        }
        CP_COMMIT();
    };
    auto load_v = [&](int k0) {
#pragma unroll
        for (int i2 = 0; i2 < 4; ++i2) {
            const int e = i2 * 128 + tid;
            const int row = e >> 3, ch = e & 7;
            const uint32_t doff = (uint32_t)(ch * 1024 + row * 16);
            CP_ASYNC16(vb_h + doff, Vh + (size_t)(k0 + row) * HD + ch * 8);
            CP_ASYNC16(vb_l + doff, Vl + (size_t)(k0 + row) * HD + ch * 8);
        }
        CP_COMMIT();
    };

    load_k(0);

    for (int it = 0; it < nt; ++it) {
        const int k0 = it * 64;

        CP_WAIT(0);
        if (tid < 64)
            maskadd[tid] = mrow[k0 + tid] ? -1e30f : 0.f;
        __syncthreads();
        load_v(k0);

        // ---- S = Q K^T (3-term, term-outer within each ks)
        float sacc[8][4];
#pragma unroll
        for (int j = 0; j < 8; ++j)
#pragma unroll
            for (int c = 0; c < 4; ++c) sacc[j][c] = 0.f;

#pragma unroll
        for (int ks = 0; ks < 4; ++ks) {
            uint32_t kfh[8][2], kfl[8][2];
#pragma unroll
            for (int grp = 0; grp < 4; ++grp) {
                const uint32_t a = (uint32_t)((2 * ks + (lane >> 4)) * 1024 +
                                              (grp * 16 + (lane & 15)) * 16);
                uint32_t r[4];
                ldsm_x4(r, kb_h + a);
                kfh[2*grp][0] = r[0]; kfh[2*grp][1] = r[2];
                kfh[2*grp+1][0] = r[1]; kfh[2*grp+1][1] = r[3];
                ldsm_x4(r, kb_l + a);
                kfl[2*grp][0] = r[0]; kfl[2*grp][1] = r[2];
                kfl[2*grp+1][0] = r[1]; kfl[2*grp+1][1] = r[3];
            }
#pragma unroll
            for (int j = 0; j < 8; ++j)
                mma_bf16(sacc[j], qfh[ks], kfh[j]);
#pragma unroll
            for (int j = 0; j < 8; ++j)
                mma_bf16(sacc[j], qfl[ks], kfh[j]);
#pragma unroll
            for (int j = 0; j < 8; ++j)
                mma_bf16(sacc[j], qfh[ks], kfl[j]);
        }

        // ---- softmax (online)
        const bool diag = (k0 == q0);
        float mx0 = -1e30f, mx1 = -1e30f;
#pragma unroll
        for (int j = 0; j < 8; ++j) {
            const float2 ma = *(const float2*)&maskadd[8 * j + 2 * t];
            float s0 = sacc[j][0] + ma.x;
            float s1 = sacc[j][1] + ma.y;
            float s2 = sacc[j][2] + ma.x;
            float s3 = sacc[j][3] + ma.y;
            if (diag) {
                const int key = k0 + 8 * j + 2 * t;
                if (key     > qg)     s0 = -1e30f;
                if (key + 1 > qg)     s1 = -1e30f;
                if (key     > qg + 8) s2 = -1e30f;
                if (key + 1 > qg + 8) s3 = -1e30f;
            }
            sacc[j][0] = s0; sacc[j][1] = s1; sacc[j][2] = s2; sacc[j][3] = s3;
            mx0 = fmaxf(mx0, fmaxf(s0, s1));
            mx1 = fmaxf(mx1, fmaxf(s2, s3));
        }
        mx0 = fmaxf(mx0, __shfl_xor_sync(0xFFFFFFFFu, mx0, 1));
        mx0 = fmaxf(mx0, __shfl_xor_sync(0xFFFFFFFFu, mx0, 2));
        mx1 = fmaxf(mx1, __shfl_xor_sync(0xFFFFFFFFu, mx1, 1));
        mx1 = fmaxf(mx1, __shfl_xor_sync(0xFFFFFFFFu, mx1, 2));
        const float mn0 = fmaxf(m0, mx0), mn1 = fmaxf(m1, mx1);
        const float cr0 = fast_exp(m0 - mn0), cr1 = fast_exp(m1 - mn1);
        m0 = mn0; m1 = mn1;
        l0 *= cr0; l1 *= cr1;
#pragma unroll
        for (int j = 0; j < 8; ++j) {
            oacc[j][0] *= cr0; oacc[j][1] *= cr0;
            oacc[j][2] *= cr1; oacc[j][3] *= cr1;
        }

        float sum0 = 0.f, sum1 = 0.f;
        uint32_t pfh[4][4], pfl[4][4];
#pragma unroll
        for (int j = 0; j < 8; ++j) {
            const float p0 = fast_exp(sacc[j][0] - mn0);
            const float p1 = fast_exp(sacc[j][1] - mn0);
            const float p2 = fast_exp(sacc[j][2] - mn1);
            const float p3 = fast_exp(sacc[j][3] - mn1);
            sum0 += p0 + p1; sum1 += p2 + p3;
            const uint32_t hi01 = prmt_hi(p0, p1);
            const uint32_t hi23 = prmt_hi(p2, p3);
            const uint32_t lo01 = pack_bf16x2(p0 - trunc_bf16(p0), p1 - trunc_bf16(p1));
            const uint32_t lo23 = pack_bf16x2(p2 - trunc_bf16(p2), p3 - trunc_bf16(p3));
            const int kk = j >> 1, sl = (j & 1) * 2;
            pfh[kk][sl + 0] = hi01; pfh[kk][sl + 1] = hi23;
            pfl[kk][sl + 0] = lo01; pfl[kk][sl + 1] = lo23;
        }
        sum0 += __shfl_xor_sync(0xFFFFFFFFu, sum0, 1);
        sum0 += __shfl_xor_sync(0xFFFFFFFFu, sum0, 2);
        sum1 += __shfl_xor_sync(0xFFFFFFFFu, sum1, 1);
        sum1 += __shfl_xor_sync(0xFFFFFFFFu, sum1, 2);
        l0 += sum0; l1 += sum1;

        CP_WAIT(0);
        __syncthreads();
        if (it + 1 < nt) load_k(k0 + 64);

        // ---- O += P V (3-term, term-outer within each kp)
#pragma unroll
        for (int kp = 0; kp < 4; ++kp) {
            uint32_t vfh[8][2], vfl[8][2];
#pragma unroll
            for (int db = 0; db < 4; ++db) {
                const uint32_t a = (uint32_t)((2 * db + (lane >> 4)) * 1024 +
                                              (kp * 16 + (lane & 15)) * 16);
                uint32_t r[4];
                ldsm_x4t(r, vb_h + a);
                vfh[2*db][0] = r[0]; vfh[2*db][1] = r[1];
                vfh[2*db+1][0] = r[2]; vfh[2*db+1][1] = r[3];
                ldsm_x4t(r, vb_l + a);
                vfl[2*db][0] = r[0]; vfl[2*db][1] = r[1];
                vfl[2*db+1][0] = r[2]; vfl[2*db+1][1] = r[3];
            }
#pragma unroll
            for (int j = 0; j < 8; ++j)
                mma_bf16(oacc[j], pfh[kp], vfh[j]);
#pragma unroll
            for (int j = 0; j < 8; ++j)
                mma_bf16(oacc[j], pfl[kp], vfh[j]);
#pragma unroll
            for (int j = 0; j < 8; ++j)
                mma_bf16(oacc[j], pfh[kp], vfl[j]);
        }
    }

    // ---- epilogue
    const float inv0 = 1.f / l0;
    const float inv1 = 1.f / l1;
    __nv_bfloat16* oh0 = g_ath + ((size_t)b * Sdim + qg) * Cdim + h * HD;
    __nv_bfloat16* ol0 = g_atl + ((size_t)b * Sdim + qg) * Cdim + h * HD;
    __nv_bfloat16* oh1 = oh0 + 8 * Cdim;
    __nv_bfloat16* ol1 = ol0 + 8 * Cdim;
#pragma unroll
    for (int j = 0; j < 8; ++j) {
        const int d = 8 * j + 2 * t;
        const float o0 = oacc[j][0] * inv0, o1 = oacc[j][1] * inv0;
        const float o2 = oacc[j][2] * inv1, o3 = oacc[j][3] * inv1;
        *(uint32_t*)(oh0 + d) = prmt_hi(o0, o1);
        *(uint32_t*)(ol0 + d) = pack_bf16x2(o0 - trunc_bf16(o0), o1 - trunc_bf16(o1));
        *(uint32_t*)(oh1 + d) = prmt_hi(o2, o3);
        *(uint32_t*)(ol1 + d) = pack_bf16x2(o2 - trunc_bf16(o2), o3 - trunc_bf16(o3));
    }
}

// ---------------------------------------------------------------------------
extern "C" void kernel_launch(void* const* d_in, const int* in_sizes, int n_in,
                              void* d_out, int out_size)
{
    const float* x     = (const float*)d_in[0];
    const float* y     = (const float*)d_in[1];
    const unsigned char* mask = (const unsigned char*)d_in[2];
    const float* Wq_b  = (const float*)d_in[4];
    const float* Wkv_b = (const float*)d_in[6];
    const float* Wo_b  = (const float*)d_in[8];
    float* out = (float*)d_out;

    const int nx = Mrows * Cdim / 4;
    split_k<0><<<(nx + 255) / 256, 256>>>((const float4*)x, nx);
    split_k<1><<<(nx + 255) / 256, 256>>>((const float4*)y, nx);
    const int nq = Cdim * Cdim / 4;
    split_k<2><<<(nq + 255) / 256, 256>>>((const float4*)d_in[3], nq);   // Wq_w
    const int nkv = 2 * Cdim * Cdim / 4;
    split_k<3><<<(nkv + 255) / 256, 256>>>((const float4*)d_in[5], nkv); // Wkv_w
    split_k<4><<<(nq + 255) / 256, 256>>>((const float4*)d_in[7], nq);   // Wo_w

    gemm_tc<0><<<dim3(Cdim / 128, Mrows / 128), 256>>>(Wq_b, nullptr);
    gemm_tc<1><<<dim3(2 * Cdim / 128, Mrows / 128), 256>>>(Wkv_b, nullptr);
    attn_tc<<<dim3(Sdim / 64, NH, Bdim), 128>>>(mask);
    gemm_tc<2><<<dim3(Cdim / 128, Mrows / 128), 256>>>(Wo_b, out);
}

// round 8
// speedup vs baseline: 5.7797x; 2.2839x over previous
#include <cuda_runtime.h>
#include <cuda_fp16.h>
#include <cstdint>

// Problem constants
#define Bdim 4
#define Sdim 2048
#define Cdim 1024
#define NH   16
#define HD   64
#define Mrows (Bdim * Sdim)   // 8192

// ---------------------------------------------------------------------------
// Scratch (__device__ globals; referenced ONLY from device code)
// ---------------------------------------------------------------------------
__device__ __align__(16) __half g_q[Bdim * NH * Sdim * HD];
__device__ __align__(16) __half g_k[Bdim * NH * Sdim * HD];
__device__ __align__(16) __half g_v[Bdim * NH * Sdim * HD];

__device__ __align__(16) __half g_x[Mrows * Cdim];
__device__ __align__(16) __half g_y[Mrows * Cdim];
__device__ __align__(16) __half g_at[Mrows * Cdim];
__device__ __align__(16) __half g_wq[Cdim * Cdim];
__device__ __align__(16) __half g_wkv[2 * Cdim * Cdim];
__device__ __align__(16) __half g_wo[Cdim * Cdim];

// ---------------------------------------------------------------------------
// PTX helpers (base sm_103 ISA: cp.async, ldmatrix, mma.sync)
// ---------------------------------------------------------------------------
__device__ __forceinline__ uint32_t smem_u32(const void* p) {
    uint32_t a;
    asm("{ .reg .u64 t; cvta.to.shared.u64 t, %1; cvt.u32.u64 %0, t; }"
        : "=r"(a) : "l"(p));
    return a;
}

#define CP_ASYNC16(sa, ga) \
    asm volatile("cp.async.cg.shared.global [%0], [%1], 16;" :: "r"(sa), "l"(ga) : "memory")
#define CP_COMMIT() asm volatile("cp.async.commit_group;" ::: "memory")
#define CP_WAIT(n)  asm volatile("cp.async.wait_group %0;" :: "n"(n) : "memory")

__device__ __forceinline__ void ldsm_x4(uint32_t* r, uint32_t addr) {
    asm volatile("ldmatrix.sync.aligned.m8n8.x4.shared.b16 {%0,%1,%2,%3}, [%4];"
                 : "=r"(r[0]), "=r"(r[1]), "=r"(r[2]), "=r"(r[3]) : "r"(addr));
}
__device__ __forceinline__ void ldsm_x4t(uint32_t* r, uint32_t addr) {
    asm volatile("ldmatrix.sync.aligned.m8n8.x4.trans.shared.b16 {%0,%1,%2,%3}, [%4];"
                 : "=r"(r[0]), "=r"(r[1]), "=r"(r[2]), "=r"(r[3]) : "r"(addr));
}
__device__ __forceinline__ void mma_f16(float* d, const uint32_t* a, const uint32_t* b) {
    asm volatile("mma.sync.aligned.m16n8k16.row.col.f32.f16.f16.f32 "
                 "{%0,%1,%2,%3}, {%4,%5,%6,%7}, {%8,%9}, {%0,%1,%2,%3};"
                 : "+f"(d[0]), "+f"(d[1]), "+f"(d[2]), "+f"(d[3])
                 : "r"(a[0]), "r"(a[1]), "r"(a[2]), "r"(a[3]), "r"(b[0]), "r"(b[1]));
}

// pack two fp32 -> f16x2 (v0 in low half, v1 in high half)
__device__ __forceinline__ uint32_t pack_f16x2(float v0, float v1) {
    uint32_t r;
    asm("cvt.rn.f16x2.f32 %0, %1, %2;" : "=r"(r) : "f"(v1), "f"(v0));
    return r;
}

// polynomial exp (no MUFU) — valid for x <= ~0, clamped below -80
__device__ __forceinline__ float fast_exp(float x) {
    x = fmaxf(x, -80.f);
    const float y = x * 1.4426950408889634f;
    const float tt = y + 12582912.f;
    const int   i  = __float_as_int(tt);
    const float n  = tt - 12582912.f;
    const float f  = y - n;
    float p = 0.001333355815f;
    p = fmaf(p, f, 0.009618129842f);
    p = fmaf(p, f, 0.05550410866f);
    p = fmaf(p, f, 0.2402265069f);
    p = fmaf(p, f, 0.69314718056f);
    p = fmaf(p, f, 1.0f);
    return __int_as_float(__float_as_int(p) + (i << 23));
}

// ---------------------------------------------------------------------------
// fp32 -> fp16 convert. T selects destination.
// ---------------------------------------------------------------------------
template <int T>
__global__ __launch_bounds__(256)
void convert_k(const float4* __restrict__ in, int n4)
{
    __half* dst;
    if (T == 0)      dst = g_x;
    else if (T == 1) dst = g_y;
    else if (T == 2) dst = g_wq;
    else if (T == 3) dst = g_wkv;
    else             dst = g_wo;

    const int i = blockIdx.x * 256 + threadIdx.x;
    if (i >= n4) return;
    const float4 v = in[i];
    uint2 o;
    o.x = pack_f16x2(v.x, v.y);
    o.y = pack_f16x2(v.z, v.w);
    ((uint2*)dst)[i] = o;
}

// ---------------------------------------------------------------------------
// HMMA fp16 GEMM (single term): C[m][n] = sum_k A[m][k]*W[n][k] + bias[n]
// CTA tile 128x128, K stage 32, 3-stage cp.async pipeline (48KB static).
// Tile layout: chunk-column-major, byte = ch*2048 + row*16 (ch = k/8, 0..3).
// 8 warps: 2(M) x 4(N); warp tile 64x32 = 4x4 mma tiles.
// MODE 0: Q -> g_q (scaled 0.125) [b,h,s,d]; MODE 1: K/V; MODE 2: fp32 out.
// ---------------------------------------------------------------------------
#define TILE_BYTES 8192u     // 128 rows * 32 k * 2B
#define BUF_BYTES  16384u    // A + B
#define NSTAGE     32        // K = 1024 / 32

template <int MODE>
__global__ __launch_bounds__(256)
void gemm_tc(const float* __restrict__ bias, float* __restrict__ out)
{
    const __half *A, *B;
    if (MODE == 0)      { A = g_x;  B = g_wq;  }
    else if (MODE == 1) { A = g_y;  B = g_wkv; }
    else                { A = g_at; B = g_wo;  }

    __shared__ __align__(128) char smraw[3 * BUF_BYTES];   // 48 KB static
    const uint32_t smb = smem_u32(smraw);

    const int tid = threadIdx.x;
    const int wid = tid >> 5;
    const int lane = tid & 31;
    const int m0 = blockIdx.y * 128;
    const int n0 = blockIdx.x * 128;
    const int warp_m = (wid & 1) * 64;
    const int warp_n = (wid >> 1) * 32;

    float acc[4][4][4];
#pragma unroll
    for (int i = 0; i < 4; ++i)
#pragma unroll
        for (int j = 0; j < 4; ++j)
#pragma unroll
            for (int c = 0; c < 4; ++c) acc[i][j][c] = 0.f;

    auto load_stage = [&](int s) {
        const int k0g = s * 32;
        const uint32_t bufb = smb + (uint32_t)(s % 3) * BUF_BYTES;
#pragma unroll
        for (int t = 0; t < 2; ++t) {
            const __half* base = (t == 0) ? A : B;
            const int r0 = (t == 0) ? m0 : n0;
            const uint32_t dst0 = bufb + (uint32_t)t * TILE_BYTES;
#pragma unroll
            for (int i = 0; i < 2; ++i) {
                const int e = i * 256 + tid;          // 0..511
                const int row = e >> 2, ch = e & 3;
                const __half* g = base + (size_t)(r0 + row) * Cdim + k0g + ch * 8;
                CP_ASYNC16(dst0 + (uint32_t)(ch * 2048 + row * 16), g);
            }
        }
        CP_COMMIT();
    };

    load_stage(0);
    load_stage(1);

    for (int s = 0; s < NSTAGE; ++s) {
        if (s < NSTAGE - 1) { CP_WAIT(1); }
        else                { CP_WAIT(0); }
        __syncthreads();
        if (s + 2 < NSTAGE) load_stage(s + 2);

        const uint32_t bufb = smb + (uint32_t)(s % 3) * BUF_BYTES;
        const uint32_t bA = bufb;
        const uint32_t bB = bufb + TILE_BYTES;

#pragma unroll
        for (int k16 = 0; k16 < 2; ++k16) {
            uint32_t af[4][4];
            {
                const int arow = warp_m + (lane & 15);
                const int kc = k16 * 2 + (lane >> 4);
#pragma unroll
                for (int tm = 0; tm < 4; ++tm)
                    ldsm_x4(af[tm], bA + (uint32_t)(kc * 2048 + (arow + tm * 16) * 16));
            }
            uint32_t bf[4][2];
            {
                const int g = lane >> 3;
                const int nr = (lane & 7) + ((g >> 1) << 3);
                const int kc = k16 * 2 + (g & 1);
#pragma unroll
                for (int half = 0; half < 2; ++half) {
                    const int row = warp_n + half * 16 + nr;
                    uint32_t r4[4];
                    ldsm_x4(r4, bB + (uint32_t)(kc * 2048 + row * 16));
                    bf[half * 2 + 0][0] = r4[0]; bf[half * 2 + 0][1] = r4[1];
                    bf[half * 2 + 1][0] = r4[2]; bf[half * 2 + 1][1] = r4[3];
                }
            }
#pragma unroll
            for (int tm = 0; tm < 4; ++tm)
#pragma unroll
                for (int tn = 0; tn < 4; ++tn)
                    mma_f16(acc[tm][tn], af[tm], bf[tn]);
        }
    }

    // ---- epilogue
#pragma unroll
    for (int tm = 0; tm < 4; ++tm) {
#pragma unroll
        for (int tn = 0; tn < 4; ++tn) {
            const int rbase = m0 + warp_m + tm * 16 + (lane >> 2);
            const int c = n0 + warp_n + tn * 8 + (lane & 3) * 2;
            const float b0 = bias[c], b1 = bias[c + 1];
#pragma unroll
            for (int half = 0; half < 2; ++half) {
                const int m = rbase + half * 8;
                float v0 = acc[tm][tn][half * 2 + 0] + b0;
                float v1 = acc[tm][tn][half * 2 + 1] + b1;
                if (MODE == 2) {
                    float2 o; o.x = v0; o.y = v1;
                    *(float2*)(out + (size_t)m * Cdim + c) = o;
                } else {
                    if (MODE == 0) { v0 *= 0.125f; v1 *= 0.125f; }
                    const int bb = m >> 11;
                    const int ss = m & (Sdim - 1);
                    __half* dh;
                    size_t idx;
                    if (MODE == 0) {
                        const int hh = c >> 6, dd = c & 63;
                        idx = (((size_t)bb * NH + hh) * Sdim + ss) * HD + dd;
                        dh = g_q;
                    } else {
                        const int sel = c >> 10;
                        const int rr = c & 1023;
                        const int hh = rr >> 6, dd = rr & 63;
                        idx = (((size_t)bb * NH + hh) * Sdim + ss) * HD + dd;
                        dh = sel ? g_v : g_k;
                    }
                    *(uint32_t*)(dh + idx) = pack_f16x2(v0, v1);
                }
            }
        }
    }
}

// ---------------------------------------------------------------------------
// Tensor-core fp16 flash attention (single term).
// CTA = 64 queries (4 warps x 16 rows), 64-key tiles, causal tile skip,
// staggered K/V cp.async pipeline. 16KB smem.
// ---------------------------------------------------------------------------
__global__ __launch_bounds__(128)
void attn_tc(const unsigned char* __restrict__ mask)
{
    __shared__ __align__(128) unsigned char kvraw[16384];
    __shared__ __align__(8) float maskadd[64];

    const int q0 = blockIdx.x * 64;
    const int h  = blockIdx.y;
    const int b  = blockIdx.z;
    const int tid = threadIdx.x;
    const int wid = tid >> 5;
    const int lane = tid & 31;
    const int g = lane >> 2, t = lane & 3;

    const uint32_t smb = smem_u32(kvraw);
    const uint32_t kb = smb;
    const uint32_t vb = smb + 8192;

    const size_t bh = ((size_t)b * NH + h) * Sdim;
    const __half* Q = g_q + (bh + q0) * HD;
    const __half* K = g_k + bh * HD;
    const __half* V = g_v + bh * HD;

    // ---- stage Q through K buffer, load fragments to registers
#pragma unroll
    for (int i2 = 0; i2 < 4; ++i2) {
        const int e = i2 * 128 + tid;
        const int row = e >> 3, ch = e & 7;
        CP_ASYNC16(kb + (uint32_t)(ch * 1024 + row * 16), Q + row * HD + ch * 8);
    }
    CP_COMMIT(); CP_WAIT(0);
    __syncthreads();

    uint32_t qf[4][4];
    {
        const int qrow = wid * 16 + (lane & 15);
#pragma unroll
        for (int ks = 0; ks < 4; ++ks)
            ldsm_x4(qf[ks], kb + (uint32_t)((2 * ks + (lane >> 4)) * 1024 + qrow * 16));
    }
    __syncthreads();

    float oacc[8][4];
#pragma unroll
    for (int j = 0; j < 8; ++j)
#pragma unroll
        for (int c = 0; c < 4; ++c) oacc[j][c] = 0.f;
    float m0 = -1e30f, m1 = -1e30f, l0 = 0.f, l1 = 0.f;

    const unsigned char* mrow = mask + (size_t)b * Sdim;
    const int nt = blockIdx.x + 1;
    const int qg = q0 + wid * 16 + g;

    auto load_k = [&](int k0) {
#pragma unroll
        for (int i2 = 0; i2 < 4; ++i2) {
            const int e = i2 * 128 + tid;
            const int row = e >> 3, ch = e & 7;
            CP_ASYNC16(kb + (uint32_t)(ch * 1024 + row * 16),
                       K + (size_t)(k0 + row) * HD + ch * 8);
        }
        CP_COMMIT();
    };
    auto load_v = [&](int k0) {
#pragma unroll
        for (int i2 = 0; i2 < 4; ++i2) {
            const int e = i2 * 128 + tid;
            const int row = e >> 3, ch = e & 7;
            CP_ASYNC16(vb + (uint32_t)(ch * 1024 + row * 16),
                       V + (size_t)(k0 + row) * HD + ch * 8);
        }
        CP_COMMIT();
    };

    load_k(0);

    for (int it = 0; it < nt; ++it) {
        const int k0 = it * 64;

        CP_WAIT(0);                      // K_it resident
        if (tid < 64)
            maskadd[tid] = mrow[k0 + tid] ? -1e30f : 0.f;
        __syncthreads();
        load_v(k0);                      // V_it loads under S compute

        // ---- S = Q K^T
        float sacc[8][4];
#pragma unroll
        for (int j = 0; j < 8; ++j)
#pragma unroll
            for (int c = 0; c < 4; ++c) sacc[j][c] = 0.f;

#pragma unroll
        for (int ks = 0; ks < 4; ++ks) {
            uint32_t kf[8][2];
#pragma unroll
            for (int grp = 0; grp < 4; ++grp) {
                const uint32_t a = (uint32_t)((2 * ks + (lane >> 4)) * 1024 +
                                              (grp * 16 + (lane & 15)) * 16);
                uint32_t r[4];
                ldsm_x4(r, kb + a);
                kf[2*grp][0] = r[0]; kf[2*grp][1] = r[2];
                kf[2*grp+1][0] = r[1]; kf[2*grp+1][1] = r[3];
            }
#pragma unroll
            for (int j = 0; j < 8; ++j)
                mma_f16(sacc[j], qf[ks], kf[j]);
        }

        // ---- softmax (online)
        const bool diag = (k0 == q0);
        float mx0 = -1e30f, mx1 = -1e30f;
#pragma unroll
        for (int j = 0; j < 8; ++j) {
            const float2 ma = *(const float2*)&maskadd[8 * j + 2 * t];
            float s0 = sacc[j][0] + ma.x;
            float s1 = sacc[j][1] + ma.y;
            float s2 = sacc[j][2] + ma.x;
            float s3 = sacc[j][3] + ma.y;
            if (diag) {
                const int key = k0 + 8 * j + 2 * t;
                if (key     > qg)     s0 = -1e30f;
                if (key + 1 > qg)     s1 = -1e30f;
                if (key     > qg + 8) s2 = -1e30f;
                if (key + 1 > qg + 8) s3 = -1e30f;
            }
            sacc[j][0] = s0; sacc[j][1] = s1; sacc[j][2] = s2; sacc[j][3] = s3;
            mx0 = fmaxf(mx0, fmaxf(s0, s1));
            mx1 = fmaxf(mx1, fmaxf(s2, s3));
        }
        mx0 = fmaxf(mx0, __shfl_xor_sync(0xFFFFFFFFu, mx0, 1));
        mx0 = fmaxf(mx0, __shfl_xor_sync(0xFFFFFFFFu, mx0, 2));
        mx1 = fmaxf(mx1, __shfl_xor_sync(0xFFFFFFFFu, mx1, 1));
        mx1 = fmaxf(mx1, __shfl_xor_sync(0xFFFFFFFFu, mx1, 2));
        const float mn0 = fmaxf(m0, mx0), mn1 = fmaxf(m1, mx1);
        const float cr0 = fast_exp(m0 - mn0), cr1 = fast_exp(m1 - mn1);
        m0 = mn0; m1 = mn1;
        l0 *= cr0; l1 *= cr1;
#pragma unroll
        for (int j = 0; j < 8; ++j) {
            oacc[j][0] *= cr0; oacc[j][1] *= cr0;
            oacc[j][2] *= cr1; oacc[j][3] *= cr1;
        }

        float sum0 = 0.f, sum1 = 0.f;
        uint32_t pf[4][4];
#pragma unroll
        for (int j = 0; j < 8; ++j) {
            const float p0 = fast_exp(sacc[j][0] - mn0);
            const float p1 = fast_exp(sacc[j][1] - mn0);
            const float p2 = fast_exp(sacc[j][2] - mn1);
            const float p3 = fast_exp(sacc[j][3] - mn1);
            sum0 += p0 + p1; sum1 += p2 + p3;
            const int kk = j >> 1, sl = (j & 1) * 2;
            pf[kk][sl + 0] = pack_f16x2(p0, p1);
            pf[kk][sl + 1] = pack_f16x2(p2, p3);
        }
        sum0 += __shfl_xor_sync(0xFFFFFFFFu, sum0, 1);
        sum0 += __shfl_xor_sync(0xFFFFFFFFu, sum0, 2);
        sum1 += __shfl_xor_sync(0xFFFFFFFFu, sum1, 1);
        sum1 += __shfl_xor_sync(0xFFFFFFFFu, sum1, 2);
        l0 += sum0; l1 += sum1;

        CP_WAIT(0);                      // V_it resident
        __syncthreads();
        if (it + 1 < nt) load_k(k0 + 64);

        // ---- O += P V
#pragma unroll
        for (int kp = 0; kp < 4; ++kp) {
            uint32_t vf[8][2];
#pragma unroll
            for (int db = 0; db < 4; ++db) {
                const uint32_t a = (uint32_t)((2 * db + (lane >> 4)) * 1024 +
                                              (kp * 16 + (lane & 15)) * 16);
                uint32_t r[4];
                ldsm_x4t(r, vb + a);
                vf[2*db][0] = r[0]; vf[2*db][1] = r[1];
                vf[2*db+1][0] = r[2]; vf[2*db+1][1] = r[3];
            }
#pragma unroll
            for (int j = 0; j < 8; ++j)
                mma_f16(oacc[j], pf[kp], vf[j]);
        }
    }

    // ---- epilogue: o/l -> fp16 at [b*s + q][h*64 + d]
    const float inv0 = 1.f / l0;
    const float inv1 = 1.f / l1;
    __half* o0p = g_at + ((size_t)b * Sdim + qg) * Cdim + h * HD;
    __half* o1p = o0p + 8 * Cdim;
#pragma unroll
    for (int j = 0; j < 8; ++j) {
        const int d = 8 * j + 2 * t;
        *(uint32_t*)(o0p + d) = pack_f16x2(oacc[j][0] * inv0, oacc[j][1] * inv0);
        *(uint32_t*)(o1p + d) = pack_f16x2(oacc[j][2] * inv1, oacc[j][3] * inv1);
    }
}

// ---------------------------------------------------------------------------
extern "C" void kernel_launch(void* const* d_in, const int* in_sizes, int n_in,
                              void* d_out, int out_size)
{
    const float* x     = (const float*)d_in[0];
    const float* y     = (const float*)d_in[1];
    const unsigned char* mask = (const unsigned char*)d_in[2];
    const float* Wq_b  = (const float*)d_in[4];
    const float* Wkv_b = (const float*)d_in[6];
    const float* Wo_b  = (const float*)d_in[8];
    float* out = (float*)d_out;

    const int nx = Mrows * Cdim / 4;
    convert_k<0><<<(nx + 255) / 256, 256>>>((const float4*)x, nx);
    convert_k<1><<<(nx + 255) / 256, 256>>>((const float4*)y, nx);
    const int nq = Cdim * Cdim / 4;
    convert_k<2><<<(nq + 255) / 256, 256>>>((const float4*)d_in[3], nq);   // Wq_w
    const int nkv = 2 * Cdim * Cdim / 4;
    convert_k<3><<<(nkv + 255) / 256, 256>>>((const float4*)d_in[5], nkv); // Wkv_w
    convert_k<4><<<(nq + 255) / 256, 256>>>((const float4*)d_in[7], nq);   // Wo_w

    gemm_tc<0><<<dim3(Cdim / 128, Mrows / 128), 256>>>(Wq_b, nullptr);
    gemm_tc<1><<<dim3(2 * Cdim / 128, Mrows / 128), 256>>>(Wkv_b, nullptr);
    attn_tc<<<dim3(Sdim / 64, NH, Bdim), 128>>>(mask);
    gemm_tc<2><<<dim3(Cdim / 128, Mrows / 128), 256>>>(Wo_b, out);
}

// round 9
// speedup vs baseline: 5.8705x; 1.0157x over previous
#include <cuda_runtime.h>
#include <cuda_fp16.h>
#include <cstdint>

// Problem constants
#define Bdim 4
#define Sdim 2048
#define Cdim 1024
#define NH   16
#define HD   64
#define Mrows (Bdim * Sdim)   // 8192

// ---------------------------------------------------------------------------
// Scratch (__device__ globals; referenced ONLY from device code)
// ---------------------------------------------------------------------------
__device__ __align__(16) __half g_q[Bdim * NH * Sdim * HD];
__device__ __align__(16) __half g_k[Bdim * NH * Sdim * HD];
__device__ __align__(16) __half g_v[Bdim * NH * Sdim * HD];

__device__ __align__(16) __half g_x[Mrows * Cdim];
__device__ __align__(16) __half g_y[Mrows * Cdim];
__device__ __align__(16) __half g_at[Mrows * Cdim];
__device__ __align__(16) __half g_wq[Cdim * Cdim];
__device__ __align__(16) __half g_wkv[2 * Cdim * Cdim];
__device__ __align__(16) __half g_wo[Cdim * Cdim];

// ---------------------------------------------------------------------------
// PTX helpers (base sm_103 ISA: cp.async, ldmatrix, mma.sync)
// ---------------------------------------------------------------------------
__device__ __forceinline__ uint32_t smem_u32(const void* p) {
    uint32_t a;
    asm("{ .reg .u64 t; cvta.to.shared.u64 t, %1; cvt.u32.u64 %0, t; }"
        : "=r"(a) : "l"(p));
    return a;
}

#define CP_ASYNC16(sa, ga) \
    asm volatile("cp.async.cg.shared.global [%0], [%1], 16;" :: "r"(sa), "l"(ga) : "memory")
#define CP_COMMIT() asm volatile("cp.async.commit_group;" ::: "memory")
#define CP_WAIT(n)  asm volatile("cp.async.wait_group %0;" :: "n"(n) : "memory")

__device__ __forceinline__ void ldsm_x4(uint32_t* r, uint32_t addr) {
    asm volatile("ldmatrix.sync.aligned.m8n8.x4.shared.b16 {%0,%1,%2,%3}, [%4];"
                 : "=r"(r[0]), "=r"(r[1]), "=r"(r[2]), "=r"(r[3]) : "r"(addr));
}
__device__ __forceinline__ void ldsm_x4t(uint32_t* r, uint32_t addr) {
    asm volatile("ldmatrix.sync.aligned.m8n8.x4.trans.shared.b16 {%0,%1,%2,%3}, [%4];"
                 : "=r"(r[0]), "=r"(r[1]), "=r"(r[2]), "=r"(r[3]) : "r"(addr));
}
__device__ __forceinline__ void mma_f16(float* d, const uint32_t* a, const uint32_t* b) {
    asm volatile("mma.sync.aligned.m16n8k16.row.col.f32.f16.f16.f32 "
                 "{%0,%1,%2,%3}, {%4,%5,%6,%7}, {%8,%9}, {%0,%1,%2,%3};"
                 : "+f"(d[0]), "+f"(d[1]), "+f"(d[2]), "+f"(d[3])
                 : "r"(a[0]), "r"(a[1]), "r"(a[2]), "r"(a[3]), "r"(b[0]), "r"(b[1]));
}

// pack two fp32 -> f16x2 (v0 in low half, v1 in high half)
__device__ __forceinline__ uint32_t pack_f16x2(float v0, float v1) {
    uint32_t r;
    asm("cvt.rn.f16x2.f32 %0, %1, %2;" : "=r"(r) : "f"(v1), "f"(v0));
    return r;
}

// polynomial exp (no MUFU) — valid for x <= ~0, clamped below -80
__device__ __forceinline__ float fast_exp(float x) {
    x = fmaxf(x, -80.f);
    const float y = x * 1.4426950408889634f;
    const float tt = y + 12582912.f;
    const int   i  = __float_as_int(tt);
    const float n  = tt - 12582912.f;
    const float f  = y - n;
    float p = 0.001333355815f;
    p = fmaf(p, f, 0.009618129842f);
    p = fmaf(p, f, 0.05550410866f);
    p = fmaf(p, f, 0.2402265069f);
    p = fmaf(p, f, 0.69314718056f);
    p = fmaf(p, f, 1.0f);
    return __int_as_float(__float_as_int(p) + (i << 23));
}

// ---------------------------------------------------------------------------
// Single fused fp32 -> fp16 convert over all 5 tensors.
// ---------------------------------------------------------------------------
#define NX4  (Mrows * Cdim / 4)        // 2,097,152
#define NW4  (Cdim * Cdim / 4)         //   262,144
#define NKV4 (2 * Cdim * Cdim / 4)     //   524,288
#define NTOT4 (2 * NX4 + 2 * NW4 + NKV4)

__global__ __launch_bounds__(256)
void convert_all(const float4* __restrict__ x, const float4* __restrict__ y,
                 const float4* __restrict__ wq, const float4* __restrict__ wkv,
                 const float4* __restrict__ wo)
{
    const int i = blockIdx.x * 256 + threadIdx.x;
    const float4* src;
    __half* dst;
    int si;
    if (i < NX4)                        { src = x;   dst = g_x;   si = i; }
    else if (i < 2 * NX4)               { src = y;   dst = g_y;   si = i - NX4; }
    else if (i < 2 * NX4 + NW4)         { src = wq;  dst = g_wq;  si = i - 2 * NX4; }
    else if (i < 2 * NX4 + NW4 + NKV4)  { src = wkv; dst = g_wkv; si = i - 2 * NX4 - NW4; }
    else                                { src = wo;  dst = g_wo;  si = i - 2 * NX4 - NW4 - NKV4; }
    const float4 v = src[si];
    uint2 o;
    o.x = pack_f16x2(v.x, v.y);
    o.y = pack_f16x2(v.z, v.w);
    ((uint2*)dst)[si] = o;
}

// ---------------------------------------------------------------------------
// HMMA fp16 GEMM mainloop (CTA 128x128, K stage 32, 3-stage cp.async).
// Shared between the fused QKV kernel and the O kernel via macro body.
// ---------------------------------------------------------------------------
#define TILE_BYTES 8192u     // 128 rows * 32 k * 2B
#define BUF_BYTES  16384u    // A + B
#define NSTAGE     32        // K = 1024 / 32

// Runs the pipelined mainloop; leaves results in acc[4][4][4].
#define GEMM_MAINLOOP(Aptr, Bptr)                                              \
    auto load_stage = [&](int s) {                                             \
        const int k0g = s * 32;                                                \
        const uint32_t bufb = smb + (uint32_t)(s % 3) * BUF_BYTES;             \
        _Pragma("unroll")                                                      \
        for (int tt = 0; tt < 2; ++tt) {                                       \
            const __half* base = (tt == 0) ? (Aptr) : (Bptr);                  \
            const int r0 = (tt == 0) ? m0 : n0;                                \
            const uint32_t dst0 = bufb + (uint32_t)tt * TILE_BYTES;            \
            _Pragma("unroll")                                                  \
            for (int i = 0; i < 2; ++i) {                                      \
                const int e = i * 256 + tid;                                   \
                const int row = e >> 2, ch = e & 3;                            \
                const __half* gp = base + (size_t)(r0 + row) * Cdim + k0g + ch * 8; \
                CP_ASYNC16(dst0 + (uint32_t)(ch * 2048 + row * 16), gp);       \
            }                                                                  \
        }                                                                      \
        CP_COMMIT();                                                           \
    };                                                                         \
    load_stage(0);                                                             \
    load_stage(1);                                                             \
    for (int s = 0; s < NSTAGE; ++s) {                                         \
        if (s < NSTAGE - 1) { CP_WAIT(1); }                                    \
        else                { CP_WAIT(0); }                                    \
        __syncthreads();                                                       \
        if (s + 2 < NSTAGE) load_stage(s + 2);                                 \
        const uint32_t bufb = smb + (uint32_t)(s % 3) * BUF_BYTES;             \
        const uint32_t bA = bufb;                                              \
        const uint32_t bB = bufb + TILE_BYTES;                                 \
        _Pragma("unroll")                                                      \
        for (int k16 = 0; k16 < 2; ++k16) {                                    \
            uint32_t af[4][4];                                                 \
            {                                                                  \
                const int arow = warp_m + (lane & 15);                         \
                const int kc = k16 * 2 + (lane >> 4);                          \
                _Pragma("unroll")                                              \
                for (int tm = 0; tm < 4; ++tm)                                 \
                    ldsm_x4(af[tm], bA + (uint32_t)(kc * 2048 + (arow + tm * 16) * 16)); \
            }                                                                  \
            uint32_t bf[4][2];                                                 \
            {                                                                  \
                const int gg = lane >> 3;                                      \
                const int nr = (lane & 7) + ((gg >> 1) << 3);                  \
                const int kc = k16 * 2 + (gg & 1);                             \
                _Pragma("unroll")                                              \
                for (int half = 0; half < 2; ++half) {                         \
                    const int row = warp_n + half * 16 + nr;                   \
                    uint32_t r4[4];                                            \
                    ldsm_x4(r4, bB + (uint32_t)(kc * 2048 + row * 16));        \
                    bf[half * 2 + 0][0] = r4[0]; bf[half * 2 + 0][1] = r4[1];  \
                    bf[half * 2 + 1][0] = r4[2]; bf[half * 2 + 1][1] = r4[3];  \
                }                                                              \
            }                                                                  \
            _Pragma("unroll")                                                  \
            for (int tm = 0; tm < 4; ++tm)                                     \
                _Pragma("unroll")                                              \
                for (int tn = 0; tn < 4; ++tn)                                 \
                    mma_f16(acc[tm][tn], af[tm], bf[tn]);                      \
        }                                                                      \
    }

// ---- Fused Q + KV projection.  grid (8, 64, 3):
//   z=0: Q = x @ Wq^T      -> g_q (scaled 0.125), n0 = bx*128
//   z=1: K = y @ Wkv^T[:1024]  -> g_k,  n0 = bx*128
//   z=2: V = y @ Wkv^T[1024:]  -> g_v,  n0 = 1024 + bx*128
__global__ __launch_bounds__(256)
void gemm_qkv(const float* __restrict__ Wq_b, const float* __restrict__ Wkv_b)
{
    const int z = blockIdx.z;
    const __half* A = (z == 0) ? g_x : g_y;
    const __half* B = (z == 0) ? g_wq : g_wkv;
    const float* bias = (z == 0) ? Wq_b : Wkv_b;

    __shared__ __align__(128) char smraw[3 * BUF_BYTES];   // 48 KB static
    const uint32_t smb = smem_u32(smraw);

    const int tid = threadIdx.x;
    const int wid = tid >> 5;
    const int lane = tid & 31;
    const int m0 = blockIdx.y * 128;
    const int n0 = ((z == 2) ? 1024 : 0) + blockIdx.x * 128;
    const int warp_m = (wid & 1) * 64;
    const int warp_n = (wid >> 1) * 32;

    float acc[4][4][4];
#pragma unroll
    for (int i = 0; i < 4; ++i)
#pragma unroll
        for (int j = 0; j < 4; ++j)
#pragma unroll
            for (int c = 0; c < 4; ++c) acc[i][j][c] = 0.f;

    GEMM_MAINLOOP(A, B)

    // ---- epilogue: Q (scaled) or K/V, fp16 [b,h,s,d]
#pragma unroll
    for (int tm = 0; tm < 4; ++tm) {
#pragma unroll
        for (int tn = 0; tn < 4; ++tn) {
            const int rbase = m0 + warp_m + tm * 16 + (lane >> 2);
            const int c = n0 + warp_n + tn * 8 + (lane & 3) * 2;
            const float b0 = bias[c], b1 = bias[c + 1];
#pragma unroll
            for (int half = 0; half < 2; ++half) {
                const int m = rbase + half * 8;
                float v0 = acc[tm][tn][half * 2 + 0] + b0;
                float v1 = acc[tm][tn][half * 2 + 1] + b1;
                const int bb = m >> 11;
                const int ss = m & (Sdim - 1);
                __half* dh;
                size_t idx;
                if (z == 0) {
                    v0 *= 0.125f; v1 *= 0.125f;
                    const int hh = c >> 6, dd = c & 63;
                    idx = (((size_t)bb * NH + hh) * Sdim + ss) * HD + dd;
                    dh = g_q;
                } else {
                    const int sel = c >> 10;
                    const int rr = c & 1023;
                    const int hh = rr >> 6, dd = rr & 63;
                    idx = (((size_t)bb * NH + hh) * Sdim + ss) * HD + dd;
                    dh = sel ? g_v : g_k;
                }
                *(uint32_t*)(dh + idx) = pack_f16x2(v0, v1);
            }
        }
    }
}

// ---- O projection: out = g_at @ Wo^T + b, fp32 plain [m][n]. grid (8, 64).
__global__ __launch_bounds__(256)
void gemm_o(const float* __restrict__ Wo_b, float* __restrict__ out)
{
    __shared__ __align__(128) char smraw[3 * BUF_BYTES];
    const uint32_t smb = smem_u32(smraw);

    const int tid = threadIdx.x;
    const int wid = tid >> 5;
    const int lane = tid & 31;
    const int m0 = blockIdx.y * 128;
    const int n0 = blockIdx.x * 128;
    const int warp_m = (wid & 1) * 64;
    const int warp_n = (wid >> 1) * 32;

    float acc[4][4][4];
#pragma unroll
    for (int i = 0; i < 4; ++i)
#pragma unroll
        for (int j = 0; j < 4; ++j)
#pragma unroll
            for (int c = 0; c < 4; ++c) acc[i][j][c] = 0.f;

    GEMM_MAINLOOP(g_at, g_wo)

#pragma unroll
    for (int tm = 0; tm < 4; ++tm) {
#pragma unroll
        for (int tn = 0; tn < 4; ++tn) {
            const int rbase = m0 + warp_m + tm * 16 + (lane >> 2);
            const int c = n0 + warp_n + tn * 8 + (lane & 3) * 2;
            const float b0 = Wo_b[c], b1 = Wo_b[c + 1];
#pragma unroll
            for (int half = 0; half < 2; ++half) {
                const int m = rbase + half * 8;
                float2 o;
                o.x = acc[tm][tn][half * 2 + 0] + b0;
                o.y = acc[tm][tn][half * 2 + 1] + b1;
                *(float2*)(out + (size_t)m * Cdim + c) = o;
            }
        }
    }
}

// ---------------------------------------------------------------------------
// Tensor-core fp16 flash attention with triangle pairing.
// grid (16, NH, B); CTA processes q-block bx AND q-block (31-bx):
// (bx+1) + (32-bx) = 33 key-tiles per CTA — perfectly balanced.
// ---------------------------------------------------------------------------
__global__ __launch_bounds__(128)
void attn_tc(const unsigned char* __restrict__ mask)
{
    __shared__ __align__(128) unsigned char kvraw[16384];
    __shared__ __align__(8) float maskadd[64];

    const int h  = blockIdx.y;
    const int b  = blockIdx.z;
    const int tid = threadIdx.x;
    const int wid = tid >> 5;
    const int lane = tid & 31;
    const int g = lane >> 2, t = lane & 3;

    const uint32_t smb = smem_u32(kvraw);
    const uint32_t kb = smb;
    const uint32_t vb = smb + 8192;

    const size_t bh = ((size_t)b * NH + h) * Sdim;
    const __half* K = g_k + bh * HD;
    const __half* V = g_v + bh * HD;
    const unsigned char* mrow = mask + (size_t)b * Sdim;

    auto load_k = [&](int k0) {
#pragma unroll
        for (int i2 = 0; i2 < 4; ++i2) {
            const int e = i2 * 128 + tid;
            const int row = e >> 3, ch = e & 7;
            CP_ASYNC16(kb + (uint32_t)(ch * 1024 + row * 16),
                       K + (size_t)(k0 + row) * HD + ch * 8);
        }
        CP_COMMIT();
    };
    auto load_v = [&](int k0) {
#pragma unroll
        for (int i2 = 0; i2 < 4; ++i2) {
            const int e = i2 * 128 + tid;
            const int row = e >> 3, ch = e & 7;
            CP_ASYNC16(vb + (uint32_t)(ch * 1024 + row * 16),
                       V + (size_t)(k0 + row) * HD + ch * 8);
        }
        CP_COMMIT();
    };

#pragma unroll 1
    for (int sub = 0; sub < 2; ++sub) {
        const int qblk = (sub == 0) ? (int)blockIdx.x
                                    : (Sdim / 64 - 1 - (int)blockIdx.x);
        const int q0 = qblk * 64;
        const int nt = qblk + 1;
        const int qg = q0 + wid * 16 + g;
        const __half* Q = g_q + (bh + q0) * HD;

        // ---- stage Q through K buffer, load fragments
#pragma unroll
        for (int i2 = 0; i2 < 4; ++i2) {
            const int e = i2 * 128 + tid;
            const int row = e >> 3, ch = e & 7;
            CP_ASYNC16(kb + (uint32_t)(ch * 1024 + row * 16), Q + row * HD + ch * 8);
        }
        CP_COMMIT(); CP_WAIT(0);
        __syncthreads();

        uint32_t qf[4][4];
        {
            const int qrow = wid * 16 + (lane & 15);
#pragma unroll
            for (int ks = 0; ks < 4; ++ks)
                ldsm_x4(qf[ks], kb + (uint32_t)((2 * ks + (lane >> 4)) * 1024 + qrow * 16));
        }
        __syncthreads();

        float oacc[8][4];
#pragma unroll
        for (int j = 0; j < 8; ++j)
#pragma unroll
            for (int c = 0; c < 4; ++c) oacc[j][c] = 0.f;
        float m0 = -1e30f, m1 = -1e30f, l0 = 0.f, l1 = 0.f;

        load_k(0);

        for (int it = 0; it < nt; ++it) {
            const int k0 = it * 64;

            CP_WAIT(0);                      // K_it resident
            if (tid < 64)
                maskadd[tid] = mrow[k0 + tid] ? -1e30f : 0.f;
            __syncthreads();
            load_v(k0);                      // V_it loads under S compute

            // ---- S = Q K^T
            float sacc[8][4];
#pragma unroll
            for (int j = 0; j < 8; ++j)
#pragma unroll
                for (int c = 0; c < 4; ++c) sacc[j][c] = 0.f;

#pragma unroll
            for (int ks = 0; ks < 4; ++ks) {
                uint32_t kf[8][2];
#pragma unroll
                for (int grp = 0; grp < 4; ++grp) {
                    const uint32_t a = (uint32_t)((2 * ks + (lane >> 4)) * 1024 +
                                                  (grp * 16 + (lane & 15)) * 16);
                    uint32_t r[4];
                    ldsm_x4(r, kb + a);
                    kf[2*grp][0] = r[0]; kf[2*grp][1] = r[2];
                    kf[2*grp+1][0] = r[1]; kf[2*grp+1][1] = r[3];
                }
#pragma unroll
                for (int j = 0; j < 8; ++j)
                    mma_f16(sacc[j], qf[ks], kf[j]);
            }

            // ---- softmax (online)
            const bool diag = (k0 == q0);
            float mx0 = -1e30f, mx1 = -1e30f;
#pragma unroll
            for (int j = 0; j < 8; ++j) {
                const float2 ma = *(const float2*)&maskadd[8 * j + 2 * t];
                float s0 = sacc[j][0] + ma.x;
                float s1 = sacc[j][1] + ma.y;
                float s2 = sacc[j][2] + ma.x;
                float s3 = sacc[j][3] + ma.y;
                if (diag) {
                    const int key = k0 + 8 * j + 2 * t;
                    if (key     > qg)     s0 = -1e30f;
                    if (key + 1 > qg)     s1 = -1e30f;
                    if (key     > qg + 8) s2 = -1e30f;
                    if (key + 1 > qg + 8) s3 = -1e30f;
                }
                sacc[j][0] = s0; sacc[j][1] = s1; sacc[j][2] = s2; sacc[j][3] = s3;
                mx0 = fmaxf(mx0, fmaxf(s0, s1));
                mx1 = fmaxf(mx1, fmaxf(s2, s3));
            }
            mx0 = fmaxf(mx0, __shfl_xor_sync(0xFFFFFFFFu, mx0, 1));
            mx0 = fmaxf(mx0, __shfl_xor_sync(0xFFFFFFFFu, mx0, 2));
            mx1 = fmaxf(mx1, __shfl_xor_sync(0xFFFFFFFFu, mx1, 1));
            mx1 = fmaxf(mx1, __shfl_xor_sync(0xFFFFFFFFu, mx1, 2));
            const float mn0 = fmaxf(m0, mx0), mn1 = fmaxf(m1, mx1);
            const float cr0 = fast_exp(m0 - mn0), cr1 = fast_exp(m1 - mn1);
            m0 = mn0; m1 = mn1;
            l0 *= cr0; l1 *= cr1;
#pragma unroll
            for (int j = 0; j < 8; ++j) {
                oacc[j][0] *= cr0; oacc[j][1] *= cr0;
                oacc[j][2] *= cr1; oacc[j][3] *= cr1;
            }

            float sum0 = 0.f, sum1 = 0.f;
            uint32_t pf[4][4];
#pragma unroll
            for (int j = 0; j < 8; ++j) {
                const float p0 = fast_exp(sacc[j][0] - mn0);
                const float p1 = fast_exp(sacc[j][1] - mn0);
                const float p2 = fast_exp(sacc[j][2] - mn1);
                const float p3 = fast_exp(sacc[j][3] - mn1);
                sum0 += p0 + p1; sum1 += p2 + p3;
                const int kk = j >> 1, sl = (j & 1) * 2;
                pf[kk][sl + 0] = pack_f16x2(p0, p1);
                pf[kk][sl + 1] = pack_f16x2(p2, p3);
            }
            sum0 += __shfl_xor_sync(0xFFFFFFFFu, sum0, 1);
            sum0 += __shfl_xor_sync(0xFFFFFFFFu, sum0, 2);
            sum1 += __shfl_xor_sync(0xFFFFFFFFu, sum1, 1);
            sum1 += __shfl_xor_sync(0xFFFFFFFFu, sum1, 2);
            l0 += sum0; l1 += sum1;

            CP_WAIT(0);                      // V_it resident
            __syncthreads();
            if (it + 1 < nt) load_k(k0 + 64);

            // ---- O += P V
#pragma unroll
            for (int kp = 0; kp < 4; ++kp) {
                uint32_t vf[8][2];
#pragma unroll
                for (int db = 0; db < 4; ++db) {
                    const uint32_t a = (uint32_t)((2 * db + (lane >> 4)) * 1024 +
                                                  (kp * 16 + (lane & 15)) * 16);
                    uint32_t r[4];
                    ldsm_x4t(r, vb + a);
                    vf[2*db][0] = r[0]; vf[2*db][1] = r[1];
                    vf[2*db+1][0] = r[2]; vf[2*db+1][1] = r[3];
                }
#pragma unroll
                for (int j = 0; j < 8; ++j)
                    mma_f16(oacc[j], pf[kp], vf[j]);
            }
        }

        // ---- epilogue: o/l -> fp16 at [b*s + q][h*64 + d]
        const float inv0 = 1.f / l0;
        const float inv1 = 1.f / l1;
        __half* o0p = g_at + ((size_t)b * Sdim + qg) * Cdim + h * HD;
        __half* o1p = o0p + 8 * Cdim;
#pragma unroll
        for (int j = 0; j < 8; ++j) {
            const int d = 8 * j + 2 * t;
            *(uint32_t*)(o0p + d) = pack_f16x2(oacc[j][0] * inv0, oacc[j][1] * inv0);
            *(uint32_t*)(o1p + d) = pack_f16x2(oacc[j][2] * inv1, oacc[j][3] * inv1);
        }
        __syncthreads();   // kb/vb reuse safety across sub iterations
    }
}

// ---------------------------------------------------------------------------
extern "C" void kernel_launch(void* const* d_in, const int* in_sizes, int n_in,
                              void* d_out, int out_size)
{
    const float* x     = (const float*)d_in[0];
    const float* y     = (const float*)d_in[1];
    const unsigned char* mask = (const unsigned char*)d_in[2];
    const float* Wq_b  = (const float*)d_in[4];
    const float* Wkv_b = (const float*)d_in[6];
    const float* Wo_b  = (const float*)d_in[8];
    float* out = (float*)d_out;

    convert_all<<<NTOT4 / 256, 256>>>((const float4*)x, (const float4*)y,
                                      (const float4*)d_in[3], (const float4*)d_in[5],
                                      (const float4*)d_in[7]);
    gemm_qkv<<<dim3(8, 64, 3), 256>>>(Wq_b, Wkv_b);
    attn_tc<<<dim3(Sdim / 128, NH, Bdim), 128>>>(mask);
    gemm_o<<<dim3(8, 64), 256>>>(Wo_b, out);
}

// round 10
// speedup vs baseline: 5.8800x; 1.0016x over previous
#include <cuda_runtime.h>
#include <cuda_fp16.h>
#include <cstdint>

// Problem constants
#define Bdim 4
#define Sdim 2048
#define Cdim 1024
#define NH   16
#define HD   64
#define Mrows (Bdim * Sdim)   // 8192

// ---------------------------------------------------------------------------
// Scratch (__device__ globals; referenced ONLY from device code)
// ---------------------------------------------------------------------------
__device__ __align__(16) __half g_q[Bdim * NH * Sdim * HD];
__device__ __align__(16) __half g_k[Bdim * NH * Sdim * HD];
__device__ __align__(16) __half g_v[Bdim * NH * Sdim * HD];

__device__ __align__(16) __half g_x[Mrows * Cdim];
__device__ __align__(16) __half g_y[Mrows * Cdim];
__device__ __align__(16) __half g_at[Mrows * Cdim];
__device__ __align__(16) __half g_wq[Cdim * Cdim];
__device__ __align__(16) __half g_wkv[2 * Cdim * Cdim];
__device__ __align__(16) __half g_wo[Cdim * Cdim];

// ---------------------------------------------------------------------------
// PTX helpers (base sm_103 ISA: cp.async, ldmatrix, mma.sync)
// ---------------------------------------------------------------------------
__device__ __forceinline__ uint32_t smem_u32(const void* p) {
    uint32_t a;
    asm("{ .reg .u64 t; cvta.to.shared.u64 t, %1; cvt.u32.u64 %0, t; }"
        : "=r"(a) : "l"(p));
    return a;
}

#define CP_ASYNC16(sa, ga) \
    asm volatile("cp.async.cg.shared.global [%0], [%1], 16;" :: "r"(sa), "l"(ga) : "memory")
#define CP_COMMIT() asm volatile("cp.async.commit_group;" ::: "memory")
#define CP_WAIT(n)  asm volatile("cp.async.wait_group %0;" :: "n"(n) : "memory")

__device__ __forceinline__ void ldsm_x4(uint32_t* r, uint32_t addr) {
    asm volatile("ldmatrix.sync.aligned.m8n8.x4.shared.b16 {%0,%1,%2,%3}, [%4];"
                 : "=r"(r[0]), "=r"(r[1]), "=r"(r[2]), "=r"(r[3]) : "r"(addr));
}
__device__ __forceinline__ void ldsm_x4t(uint32_t* r, uint32_t addr) {
    asm volatile("ldmatrix.sync.aligned.m8n8.x4.trans.shared.b16 {%0,%1,%2,%3}, [%4];"
                 : "=r"(r[0]), "=r"(r[1]), "=r"(r[2]), "=r"(r[3]) : "r"(addr));
}
__device__ __forceinline__ void mma_f16(float* d, const uint32_t* a, const uint32_t* b) {
    asm volatile("mma.sync.aligned.m16n8k16.row.col.f32.f16.f16.f32 "
                 "{%0,%1,%2,%3}, {%4,%5,%6,%7}, {%8,%9}, {%0,%1,%2,%3};"
                 : "+f"(d[0]), "+f"(d[1]), "+f"(d[2]), "+f"(d[3])
                 : "r"(a[0]), "r"(a[1]), "r"(a[2]), "r"(a[3]), "r"(b[0]), "r"(b[1]));
}

// pack two fp32 -> f16x2 (v0 in low half, v1 in high half)
__device__ __forceinline__ uint32_t pack_f16x2(float v0, float v1) {
    uint32_t r;
    asm("cvt.rn.f16x2.f32 %0, %1, %2;" : "=r"(r) : "f"(v1), "f"(v0));
    return r;
}

// polynomial exp (no MUFU) — valid for x <= ~0, clamped below -80
__device__ __forceinline__ float fast_exp(float x) {
    x = fmaxf(x, -80.f);
    const float y = x * 1.4426950408889634f;
    const float tt = y + 12582912.f;
    const int   i  = __float_as_int(tt);
    const float n  = tt - 12582912.f;
    const float f  = y - n;
    float p = 0.001333355815f;
    p = fmaf(p, f, 0.009618129842f);
    p = fmaf(p, f, 0.05550410866f);
    p = fmaf(p, f, 0.2402265069f);
    p = fmaf(p, f, 0.69314718056f);
    p = fmaf(p, f, 1.0f);
    return __int_as_float(__float_as_int(p) + (i << 23));
}

// ---------------------------------------------------------------------------
// Single fused fp32 -> fp16 convert over all 5 tensors.
// ---------------------------------------------------------------------------
#define NX4  (Mrows * Cdim / 4)
#define NW4  (Cdim * Cdim / 4)
#define NKV4 (2 * Cdim * Cdim / 4)
#define NTOT4 (2 * NX4 + 2 * NW4 + NKV4)

__global__ __launch_bounds__(256)
void convert_all(const float4* __restrict__ x, const float4* __restrict__ y,
                 const float4* __restrict__ wq, const float4* __restrict__ wkv,
                 const float4* __restrict__ wo)
{
    const int i = blockIdx.x * 256 + threadIdx.x;
    const float4* src;
    __half* dst;
    int si;
    if (i < NX4)                        { src = x;   dst = g_x;   si = i; }
    else if (i < 2 * NX4)               { src = y;   dst = g_y;   si = i - NX4; }
    else if (i < 2 * NX4 + NW4)         { src = wq;  dst = g_wq;  si = i - 2 * NX4; }
    else if (i < 2 * NX4 + NW4 + NKV4)  { src = wkv; dst = g_wkv; si = i - 2 * NX4 - NW4; }
    else                                { src = wo;  dst = g_wo;  si = i - 2 * NX4 - NW4 - NKV4; }
    const float4 v = src[si];
    uint2 o;
    o.x = pack_f16x2(v.x, v.y);
    o.y = pack_f16x2(v.z, v.w);
    ((uint2*)dst)[si] = o;
}

// ---------------------------------------------------------------------------
// HMMA fp16 GEMM mainloop: CTA tile 128(M) x 256(N), K stage 32,
// 2-stage cp.async pipeline, 48KB static smem (A 8KB + B 16KB per stage).
// 8 warps: 2(M) x 4(N); warp tile 64x64 = 4x8 mma tiles -> 64 MMA/warp/stage,
// LDSM:MMA = 8:32 per k16. One barrier per stage.
// A layout: ch*2048 + row*16 (128 rows); B layout: ch*4096 + row*16 (256 rows).
// ---------------------------------------------------------------------------
#define A_TILE  8192u
#define B_TILE  16384u
#define STAGE_B 24576u
#define NSTAGE  32           // K = 1024 / 32

#define GEMM_MAINLOOP(Aptr, Bptr)                                              \
    auto load_stage = [&](int s) {                                             \
        const int k0g = s * 32;                                                \
        const uint32_t bufb = smb + (uint32_t)(s & 1) * STAGE_B;               \
        _Pragma("unroll")                                                      \
        for (int i = 0; i < 2; ++i) {                                          \
            const int e = i * 256 + tid;                                       \
            const int row = e >> 2, ch = e & 3;                                \
            const __half* gp = (Aptr) + (size_t)(m0 + row) * Cdim + k0g + ch * 8; \
            CP_ASYNC16(bufb + (uint32_t)(ch * 2048 + row * 16), gp);           \
        }                                                                      \
        _Pragma("unroll")                                                      \
        for (int i = 0; i < 4; ++i) {                                          \
            const int e = i * 256 + tid;                                       \
            const int row = e >> 2, ch = e & 3;                                \
            const __half* gp = (Bptr) + (size_t)(n0 + row) * Cdim + k0g + ch * 8; \
            CP_ASYNC16(bufb + A_TILE + (uint32_t)(ch * 4096 + row * 16), gp);  \
        }                                                                      \
        CP_COMMIT();                                                           \
    };                                                                         \
    load_stage(0);                                                             \
    for (int s = 0; s < NSTAGE; ++s) {                                         \
        CP_WAIT(0);                                                            \
        __syncthreads();                                                       \
        if (s + 1 < NSTAGE) load_stage(s + 1);                                 \
        const uint32_t bufb = smb + (uint32_t)(s & 1) * STAGE_B;               \
        const uint32_t bA = bufb;                                              \
        const uint32_t bB = bufb + A_TILE;                                     \
        _Pragma("unroll")                                                      \
        for (int k16 = 0; k16 < 2; ++k16) {                                    \
            uint32_t af[4][4];                                                 \
            {                                                                  \
                const int arow = warp_m + (lane & 15);                         \
                const int kc = k16 * 2 + (lane >> 4);                          \
                _Pragma("unroll")                                              \
                for (int tm = 0; tm < 4; ++tm)                                 \
                    ldsm_x4(af[tm], bA + (uint32_t)(kc * 2048 + (arow + tm * 16) * 16)); \
            }                                                                  \
            uint32_t bf[8][2];                                                 \
            {                                                                  \
                const int gg = lane >> 3;                                      \
                const int nr = (lane & 7) + ((gg >> 1) << 3);                  \
                const int kc = k16 * 2 + (gg & 1);                             \
                _Pragma("unroll")                                              \
                for (int half = 0; half < 4; ++half) {                         \
                    const int row = warp_n + half * 16 + nr;                   \
                    uint32_t r4[4];                                            \
                    ldsm_x4(r4, bB + (uint32_t)(kc * 4096 + row * 16));        \
                    bf[half * 2 + 0][0] = r4[0]; bf[half * 2 + 0][1] = r4[1];  \
                    bf[half * 2 + 1][0] = r4[2]; bf[half * 2 + 1][1] = r4[3];  \
                }                                                              \
            }                                                                  \
            _Pragma("unroll")                                                  \
            for (int tm = 0; tm < 4; ++tm)                                     \
                _Pragma("unroll")                                              \
                for (int tn = 0; tn < 8; ++tn)                                 \
                    mma_f16(acc[tm][tn], af[tm], bf[tn]);                      \
        }                                                                      \
    }

// ---- Fused Q + KV projection.  grid (4, 64, 3):
//   z=0: Q = x @ Wq^T -> g_q (scaled 0.125), n0 = bx*256
//   z=1: K half of Wkv, n0 = bx*256
//   z=2: V half of Wkv, n0 = 1024 + bx*256
__global__ __launch_bounds__(256)
void gemm_qkv(const float* __restrict__ Wq_b, const float* __restrict__ Wkv_b)
{
    const int z = blockIdx.z;
    const __half* A = (z == 0) ? g_x : g_y;
    const __half* B = (z == 0) ? g_wq : g_wkv;
    const float* bias = (z == 0) ? Wq_b : Wkv_b;

    __shared__ __align__(128) char smraw[2 * STAGE_B];   // 48 KB static
    const uint32_t smb = smem_u32(smraw);

    const int tid = threadIdx.x;
    const int wid = tid >> 5;
    const int lane = tid & 31;
    const int m0 = blockIdx.y * 128;
    const int n0 = ((z == 2) ? 1024 : 0) + blockIdx.x * 256;
    const int warp_m = (wid & 1) * 64;
    const int warp_n = (wid >> 1) * 64;

    float acc[4][8][4];
#pragma unroll
    for (int i = 0; i < 4; ++i)
#pragma unroll
        for (int j = 0; j < 8; ++j)
#pragma unroll
            for (int c = 0; c < 4; ++c) acc[i][j][c] = 0.f;

    GEMM_MAINLOOP(A, B)

    // ---- epilogue: Q (scaled) or K/V, fp16 [b,h,s,d]
#pragma unroll
    for (int tm = 0; tm < 4; ++tm) {
#pragma unroll
        for (int tn = 0; tn < 8; ++tn) {
            const int rbase = m0 + warp_m + tm * 16 + (lane >> 2);
            const int c = n0 + warp_n + tn * 8 + (lane & 3) * 2;
            const float b0 = bias[c], b1 = bias[c + 1];
#pragma unroll
            for (int half = 0; half < 2; ++half) {
                const int m = rbase + half * 8;
                float v0 = acc[tm][tn][half * 2 + 0] + b0;
                float v1 = acc[tm][tn][half * 2 + 1] + b1;
                const int bb = m >> 11;
                const int ss = m & (Sdim - 1);
                __half* dh;
                size_t idx;
                if (z == 0) {
                    v0 *= 0.125f; v1 *= 0.125f;
                    const int hh = c >> 6, dd = c & 63;
                    idx = (((size_t)bb * NH + hh) * Sdim + ss) * HD + dd;
                    dh = g_q;
                } else {
                    const int sel = c >> 10;
                    const int rr = c & 1023;
                    const int hh = rr >> 6, dd = rr & 63;
                    idx = (((size_t)bb * NH + hh) * Sdim + ss) * HD + dd;
                    dh = sel ? g_v : g_k;
                }
                *(uint32_t*)(dh + idx) = pack_f16x2(v0, v1);
            }
        }
    }
}

// ---- O projection: out = g_at @ Wo^T + b, fp32 plain [m][n]. grid (4, 64).
__global__ __launch_bounds__(256)
void gemm_o(const float* __restrict__ Wo_b, float* __restrict__ out)
{
    __shared__ __align__(128) char smraw[2 * STAGE_B];
    const uint32_t smb = smem_u32(smraw);

    const int tid = threadIdx.x;
    const int wid = tid >> 5;
    const int lane = tid & 31;
    const int m0 = blockIdx.y * 128;
    const int n0 = blockIdx.x * 256;
    const int warp_m = (wid & 1) * 64;
    const int warp_n = (wid >> 1) * 64;

    float acc[4][8][4];
#pragma unroll
    for (int i = 0; i < 4; ++i)
#pragma unroll
        for (int j = 0; j < 8; ++j)
#pragma unroll
            for (int c = 0; c < 4; ++c) acc[i][j][c] = 0.f;

    GEMM_MAINLOOP(g_at, g_wo)

#pragma unroll
    for (int tm = 0; tm < 4; ++tm) {
#pragma unroll
        for (int tn = 0; tn < 8; ++tn) {
            const int rbase = m0 + warp_m + tm * 16 + (lane >> 2);
            const int c = n0 + warp_n + tn * 8 + (lane & 3) * 2;
            const float b0 = Wo_b[c], b1 = Wo_b[c + 1];
#pragma unroll
            for (int half = 0; half < 2; ++half) {
                const int m = rbase + half * 8;
                float2 o;
                o.x = acc[tm][tn][half * 2 + 0] + b0;
                o.y = acc[tm][tn][half * 2 + 1] + b1;
                *(float2*)(out + (size_t)m * Cdim + c) = o;
            }
        }
    }
}

// ---------------------------------------------------------------------------
// Tensor-core fp16 flash attention with triangle pairing (unchanged from R9).
// grid (16, NH, B); CTA does q-block bx AND q-block (31-bx): 33 tiles each.
// ---------------------------------------------------------------------------
__global__ __launch_bounds__(128)
void attn_tc(const unsigned char* __restrict__ mask)
{
    __shared__ __align__(128) unsigned char kvraw[16384];
    __shared__ __align__(8) float maskadd[64];

    const int h  = blockIdx.y;
    const int b  = blockIdx.z;
    const int tid = threadIdx.x;
    const int wid = tid >> 5;
    const int lane = tid & 31;
    const int g = lane >> 2, t = lane & 3;

    const uint32_t smb = smem_u32(kvraw);
    const uint32_t kb = smb;
    const uint32_t vb = smb + 8192;

    const size_t bh = ((size_t)b * NH + h) * Sdim;
    const __half* K = g_k + bh * HD;
    const __half* V = g_v + bh * HD;
    const unsigned char* mrow = mask + (size_t)b * Sdim;

    auto load_k = [&](int k0) {
#pragma unroll
        for (int i2 = 0; i2 < 4; ++i2) {
            const int e = i2 * 128 + tid;
            const int row = e >> 3, ch = e & 7;
            CP_ASYNC16(kb + (uint32_t)(ch * 1024 + row * 16),
                       K + (size_t)(k0 + row) * HD + ch * 8);
        }
        CP_COMMIT();
    };
    auto load_v = [&](int k0) {
#pragma unroll
        for (int i2 = 0; i2 < 4; ++i2) {
            const int e = i2 * 128 + tid;
            const int row = e >> 3, ch = e & 7;
            CP_ASYNC16(vb + (uint32_t)(ch * 1024 + row * 16),
                       V + (size_t)(k0 + row) * HD + ch * 8);
        }
        CP_COMMIT();
    };

#pragma unroll 1
    for (int sub = 0; sub < 2; ++sub) {
        const int qblk = (sub == 0) ? (int)blockIdx.x
                                    : (Sdim / 64 - 1 - (int)blockIdx.x);
        const int q0 = qblk * 64;
        const int nt = qblk + 1;
        const int qg = q0 + wid * 16 + g;
        const __half* Q = g_q + (bh + q0) * HD;

#pragma unroll
        for (int i2 = 0; i2 < 4; ++i2) {
            const int e = i2 * 128 + tid;
            const int row = e >> 3, ch = e & 7;
            CP_ASYNC16(kb + (uint32_t)(ch * 1024 + row * 16), Q + row * HD + ch * 8);
        }
        CP_COMMIT(); CP_WAIT(0);
        __syncthreads();

        uint32_t qf[4][4];
        {
            const int qrow = wid * 16 + (lane & 15);
#pragma unroll
            for (int ks = 0; ks < 4; ++ks)
                ldsm_x4(qf[ks], kb + (uint32_t)((2 * ks + (lane >> 4)) * 1024 + qrow * 16));
        }
        __syncthreads();

        float oacc[8][4];
#pragma unroll
        for (int j = 0; j < 8; ++j)
#pragma unroll
            for (int c = 0; c < 4; ++c) oacc[j][c] = 0.f;
        float m0 = -1e30f, m1 = -1e30f, l0 = 0.f, l1 = 0.f;

        load_k(0);

        for (int it = 0; it < nt; ++it) {
            const int k0 = it * 64;

            CP_WAIT(0);                      // K_it resident
            if (tid < 64)
                maskadd[tid] = mrow[k0 + tid] ? -1e30f : 0.f;
            __syncthreads();
            load_v(k0);                      // V_it loads under S compute

            float sacc[8][4];
#pragma unroll
            for (int j = 0; j < 8; ++j)
#pragma unroll
                for (int c = 0; c < 4; ++c) sacc[j][c] = 0.f;

#pragma unroll
            for (int ks = 0; ks < 4; ++ks) {
                uint32_t kf[8][2];
#pragma unroll
                for (int grp = 0; grp < 4; ++grp) {
                    const uint32_t a = (uint32_t)((2 * ks + (lane >> 4)) * 1024 +
                                                  (grp * 16 + (lane & 15)) * 16);
                    uint32_t r[4];
                    ldsm_x4(r, kb + a);
                    kf[2*grp][0] = r[0]; kf[2*grp][1] = r[2];
                    kf[2*grp+1][0] = r[1]; kf[2*grp+1][1] = r[3];
                }
#pragma unroll
                for (int j = 0; j < 8; ++j)
                    mma_f16(sacc[j], qf[ks], kf[j]);
            }

            const bool diag = (k0 == q0);
            float mx0 = -1e30f, mx1 = -1e30f;
#pragma unroll
            for (int j = 0; j < 8; ++j) {
                const float2 ma = *(const float2*)&maskadd[8 * j + 2 * t];
                float s0 = sacc[j][0] + ma.x;
                float s1 = sacc[j][1] + ma.y;
                float s2 = sacc[j][2] + ma.x;
                float s3 = sacc[j][3] + ma.y;
                if (diag) {
                    const int key = k0 + 8 * j + 2 * t;
                    if (key     > qg)     s0 = -1e30f;
                    if (key + 1 > qg)     s1 = -1e30f;
                    if (key     > qg + 8) s2 = -1e30f;
                    if (key + 1 > qg + 8) s3 = -1e30f;
                }
                sacc[j][0] = s0; sacc[j][1] = s1; sacc[j][2] = s2; sacc[j][3] = s3;
                mx0 = fmaxf(mx0, fmaxf(s0, s1));
                mx1 = fmaxf(mx1, fmaxf(s2, s3));
            }
            mx0 = fmaxf(mx0, __shfl_xor_sync(0xFFFFFFFFu, mx0, 1));
            mx0 = fmaxf(mx0, __shfl_xor_sync(0xFFFFFFFFu, mx0, 2));
            mx1 = fmaxf(mx1, __shfl_xor_sync(0xFFFFFFFFu, mx1, 1));
            mx1 = fmaxf(mx1, __shfl_xor_sync(0xFFFFFFFFu, mx1, 2));
            const float mn0 = fmaxf(m0, mx0), mn1 = fmaxf(m1, mx1);
            const float cr0 = fast_exp(m0 - mn0), cr1 = fast_exp(m1 - mn1);
            m0 = mn0; m1 = mn1;
            l0 *= cr0; l1 *= cr1;
#pragma unroll
            for (int j = 0; j < 8; ++j) {
                oacc[j][0] *= cr0; oacc[j][1] *= cr0;
                oacc[j][2] *= cr1; oacc[j][3] *= cr1;
            }

            float sum0 = 0.f, sum1 = 0.f;
            uint32_t pf[4][4];
#pragma unroll
            for (int j = 0; j < 8; ++j) {
                const float p0 = fast_exp(sacc[j][0] - mn0);
                const float p1 = fast_exp(sacc[j][1] - mn0);
                const float p2 = fast_exp(sacc[j][2] - mn1);
                const float p3 = fast_exp(sacc[j][3] - mn1);
                sum0 += p0 + p1; sum1 += p2 + p3;
                const int kk = j >> 1, sl = (j & 1) * 2;
                pf[kk][sl + 0] = pack_f16x2(p0, p1);
                pf[kk][sl + 1] = pack_f16x2(p2, p3);
            }
            sum0 += __shfl_xor_sync(0xFFFFFFFFu, sum0, 1);
            sum0 += __shfl_xor_sync(0xFFFFFFFFu, sum0, 2);
            sum1 += __shfl_xor_sync(0xFFFFFFFFu, sum1, 1);
            sum1 += __shfl_xor_sync(0xFFFFFFFFu, sum1, 2);
            l0 += sum0; l1 += sum1;

            CP_WAIT(0);                      // V_it resident
            __syncthreads();
            if (it + 1 < nt) load_k(k0 + 64);

#pragma unroll
            for (int kp = 0; kp < 4; ++kp) {
                uint32_t vf[8][2];
#pragma unroll
                for (int db = 0; db < 4; ++db) {
                    const uint32_t a = (uint32_t)((2 * db + (lane >> 4)) * 1024 +
                                                  (kp * 16 + (lane & 15)) * 16);
                    uint32_t r[4];
                    ldsm_x4t(r, vb + a);
                    vf[2*db][0] = r[0]; vf[2*db][1] = r[1];
                    vf[2*db+1][0] = r[2]; vf[2*db+1][1] = r[3];
                }
#pragma unroll
                for (int j = 0; j < 8; ++j)
                    mma_f16(oacc[j], pf[kp], vf[j]);
            }
        }

        const float inv0 = 1.f / l0;
        const float inv1 = 1.f / l1;
        __half* o0p = g_at + ((size_t)b * Sdim + qg) * Cdim + h * HD;
        __half* o1p = o0p + 8 * Cdim;
#pragma unroll
        for (int j = 0; j < 8; ++j) {
            const int d = 8 * j + 2 * t;
            *(uint32_t*)(o0p + d) = pack_f16x2(oacc[j][0] * inv0, oacc[j][1] * inv0);
            *(uint32_t*)(o1p + d) = pack_f16x2(oacc[j][2] * inv1, oacc[j][3] * inv1);
        }
        __syncthreads();   // kb/vb reuse safety across sub iterations
    }
}

// ---------------------------------------------------------------------------
extern "C" void kernel_launch(void* const* d_in, const int* in_sizes, int n_in,
                              void* d_out, int out_size)
{
    const float* x     = (const float*)d_in[0];
    const float* y     = (const float*)d_in[1];
    const unsigned char* mask = (const unsigned char*)d_in[2];
    const float* Wq_b  = (const float*)d_in[4];
    const float* Wkv_b = (const float*)d_in[6];
    const float* Wo_b  = (const float*)d_in[8];
    float* out = (float*)d_out;

    convert_all<<<NTOT4 / 256, 256>>>((const float4*)x, (const float4*)y,
                                      (const float4*)d_in[3], (const float4*)d_in[5],
                                      (const float4*)d_in[7]);
    gemm_qkv<<<dim3(4, 64, 3), 256>>>(Wq_b, Wkv_b);
    attn_tc<<<dim3(Sdim / 128, NH, Bdim), 128>>>(mask);
    gemm_o<<<dim3(4, 64), 256>>>(Wo_b, out);
}

// round 11
// speedup vs baseline: 5.9481x; 1.0116x over previous
#include <cuda_runtime.h>
#include <cuda_fp16.h>
#include <cstdint>

// Problem constants
#define Bdim 4
#define Sdim 2048
#define Cdim 1024
#define NH   16
#define HD   64
#define Mrows (Bdim * Sdim)   // 8192

// ---------------------------------------------------------------------------
// Scratch (__device__ globals; referenced ONLY from device code)
// Q/K/V stored GEMM-natural: [m][c] with m = b*S+s, c = h*64+d.
// ---------------------------------------------------------------------------
__device__ __align__(16) __half g_q[Mrows * Cdim];
__device__ __align__(16) __half g_k[Mrows * Cdim];
__device__ __align__(16) __half g_v[Mrows * Cdim];

__device__ __align__(16) __half g_x[Mrows * Cdim];
__device__ __align__(16) __half g_y[Mrows * Cdim];
__device__ __align__(16) __half g_at[Mrows * Cdim];
__device__ __align__(16) __half g_wq[Cdim * Cdim];
__device__ __align__(16) __half g_wkv[2 * Cdim * Cdim];
__device__ __align__(16) __half g_wo[Cdim * Cdim];

// ---------------------------------------------------------------------------
// PTX helpers (base sm_103 ISA: cp.async, ldmatrix, mma.sync)
// ---------------------------------------------------------------------------
__device__ __forceinline__ uint32_t smem_u32(const void* p) {
    uint32_t a;
    asm("{ .reg .u64 t; cvta.to.shared.u64 t, %1; cvt.u32.u64 %0, t; }"
        : "=r"(a) : "l"(p));
    return a;
}

#define CP_ASYNC16(sa, ga) \
    asm volatile("cp.async.cg.shared.global [%0], [%1], 16;" :: "r"(sa), "l"(ga) : "memory")
#define CP_COMMIT() asm volatile("cp.async.commit_group;" ::: "memory")
#define CP_WAIT(n)  asm volatile("cp.async.wait_group %0;" :: "n"(n) : "memory")

__device__ __forceinline__ void ldsm_x4(uint32_t* r, uint32_t addr) {
    asm volatile("ldmatrix.sync.aligned.m8n8.x4.shared.b16 {%0,%1,%2,%3}, [%4];"
                 : "=r"(r[0]), "=r"(r[1]), "=r"(r[2]), "=r"(r[3]) : "r"(addr));
}
__device__ __forceinline__ void ldsm_x4t(uint32_t* r, uint32_t addr) {
    asm volatile("ldmatrix.sync.aligned.m8n8.x4.trans.shared.b16 {%0,%1,%2,%3}, [%4];"
                 : "=r"(r[0]), "=r"(r[1]), "=r"(r[2]), "=r"(r[3]) : "r"(addr));
}
__device__ __forceinline__ void mma_f16(float* d, const uint32_t* a, const uint32_t* b) {
    asm volatile("mma.sync.aligned.m16n8k16.row.col.f32.f16.f16.f32 "
                 "{%0,%1,%2,%3}, {%4,%5,%6,%7}, {%8,%9}, {%0,%1,%2,%3};"
                 : "+f"(d[0]), "+f"(d[1]), "+f"(d[2]), "+f"(d[3])
                 : "r"(a[0]), "r"(a[1]), "r"(a[2]), "r"(a[3]), "r"(b[0]), "r"(b[1]));
}

// pack two fp32 -> f16x2 (v0 in low half, v1 in high half)
__device__ __forceinline__ uint32_t pack_f16x2(float v0, float v1) {
    uint32_t r;
    asm("cvt.rn.f16x2.f32 %0, %1, %2;" : "=r"(r) : "f"(v1), "f"(v0));
    return r;
}

// polynomial exp (no MUFU) — valid for x <= ~0, clamped below -80
__device__ __forceinline__ float fast_exp(float x) {
    x = fmaxf(x, -80.f);
    const float y = x * 1.4426950408889634f;
    const float tt = y + 12582912.f;
    const int   i  = __float_as_int(tt);
    const float n  = tt - 12582912.f;
    const float f  = y - n;
    float p = 0.001333355815f;
    p = fmaf(p, f, 0.009618129842f);
    p = fmaf(p, f, 0.05550410866f);
    p = fmaf(p, f, 0.2402265069f);
    p = fmaf(p, f, 0.69314718056f);
    p = fmaf(p, f, 1.0f);
    return __int_as_float(__float_as_int(p) + (i << 23));
}

// ---------------------------------------------------------------------------
// Single fused fp32 -> fp16 convert over all 5 tensors.
// ---------------------------------------------------------------------------
#define NX4  (Mrows * Cdim / 4)
#define NW4  (Cdim * Cdim / 4)
#define NKV4 (2 * Cdim * Cdim / 4)
#define NTOT4 (2 * NX4 + 2 * NW4 + NKV4)

__global__ __launch_bounds__(256)
void convert_all(const float4* __restrict__ x, const float4* __restrict__ y,
                 const float4* __restrict__ wq, const float4* __restrict__ wkv,
                 const float4* __restrict__ wo)
{
    const int i = blockIdx.x * 256 + threadIdx.x;
    const float4* src;
    __half* dst;
    int si;
    if (i < NX4)                        { src = x;   dst = g_x;   si = i; }
    else if (i < 2 * NX4)               { src = y;   dst = g_y;   si = i - NX4; }
    else if (i < 2 * NX4 + NW4)         { src = wq;  dst = g_wq;  si = i - 2 * NX4; }
    else if (i < 2 * NX4 + NW4 + NKV4)  { src = wkv; dst = g_wkv; si = i - 2 * NX4 - NW4; }
    else                                { src = wo;  dst = g_wo;  si = i - 2 * NX4 - NW4 - NKV4; }
    const float4 v = src[si];
    uint2 o;
    o.x = pack_f16x2(v.x, v.y);
    o.y = pack_f16x2(v.z, v.w);
    ((uint2*)dst)[si] = o;
}

// ---------------------------------------------------------------------------
// HMMA fp16 GEMM mainloop: CTA tile 128(M) x 256(N), K stage 32,
// 2-stage cp.async pipeline, 48KB static smem (A 8KB + B 16KB per stage).
// 8 warps: 2(M) x 4(N); warp tile 64x64.
// ---------------------------------------------------------------------------
#define A_TILE  8192u
#define B_TILE  16384u
#define STAGE_B 24576u
#define NSTAGE  32           // K = 1024 / 32

#define GEMM_MAINLOOP(Aptr, Bptr)                                              \
    auto load_stage = [&](int s) {                                             \
        const int k0g = s * 32;                                                \
        const uint32_t bufb = smb + (uint32_t)(s & 1) * STAGE_B;               \
        _Pragma("unroll")                                                      \
        for (int i = 0; i < 2; ++i) {                                          \
            const int e = i * 256 + tid;                                       \
            const int row = e >> 2, ch = e & 3;                                \
            const __half* gp = (Aptr) + (size_t)(m0 + row) * Cdim + k0g + ch * 8; \
            CP_ASYNC16(bufb + (uint32_t)(ch * 2048 + row * 16), gp);           \
        }                                                                      \
        _Pragma("unroll")                                                      \
        for (int i = 0; i < 4; ++i) {                                          \
            const int e = i * 256 + tid;                                       \
            const int row = e >> 2, ch = e & 3;                                \
            const __half* gp = (Bptr) + (size_t)(n0 + row) * Cdim + k0g + ch * 8; \
            CP_ASYNC16(bufb + A_TILE + (uint32_t)(ch * 4096 + row * 16), gp);  \
        }                                                                      \
        CP_COMMIT();                                                           \
    };                                                                         \
    load_stage(0);                                                             \
    for (int s = 0; s < NSTAGE; ++s) {                                         \
        CP_WAIT(0);                                                            \
        __syncthreads();                                                       \
        if (s + 1 < NSTAGE) load_stage(s + 1);                                 \
        const uint32_t bufb = smb + (uint32_t)(s & 1) * STAGE_B;               \
        const uint32_t bA = bufb;                                              \
        const uint32_t bB = bufb + A_TILE;                                     \
        _Pragma("unroll")                                                      \
        for (int k16 = 0; k16 < 2; ++k16) {                                    \
            uint32_t af[4][4];                                                 \
            {                                                                  \
                const int arow = warp_m + (lane & 15);                         \
                const int kc = k16 * 2 + (lane >> 4);                          \
                _Pragma("unroll")                                              \
                for (int tm = 0; tm < 4; ++tm)                                 \
                    ldsm_x4(af[tm], bA + (uint32_t)(kc * 2048 + (arow + tm * 16) * 16)); \
            }                                                                  \
            uint32_t bf[8][2];                                                 \
            {                                                                  \
                const int gg = lane >> 3;                                      \
                const int nr = (lane & 7) + ((gg >> 1) << 3);                  \
                const int kc = k16 * 2 + (gg & 1);                             \
                _Pragma("unroll")                                              \
                for (int half = 0; half < 4; ++half) {                         \
                    const int row = warp_n + half * 16 + nr;                   \
                    uint32_t r4[4];                                            \
                    ldsm_x4(r4, bB + (uint32_t)(kc * 4096 + row * 16));        \
                    bf[half * 2 + 0][0] = r4[0]; bf[half * 2 + 0][1] = r4[1];  \
                    bf[half * 2 + 1][0] = r4[2]; bf[half * 2 + 1][1] = r4[3];  \
                }                                                              \
            }                                                                  \
            _Pragma("unroll")                                                  \
            for (int tm = 0; tm < 4; ++tm)                                     \
                _Pragma("unroll")                                              \
                for (int tn = 0; tn < 8; ++tn)                                 \
                    mma_f16(acc[tm][tn], af[tm], bf[tn]);                      \
        }                                                                      \
    }

// ---- Fused Q + KV projection.  grid (4, 64, 3):
//   z=0: Q = x @ Wq^T -> g_q (scaled 0.125) [m][c]
//   z=1: K half of Wkv -> g_k [m][c]
//   z=2: V half of Wkv -> g_v [m][c-1024]
// Epilogue is plain coalesced [m][c] stores (same pattern as gemm_o).
__global__ __launch_bounds__(256)
void gemm_qkv(const float* __restrict__ Wq_b, const float* __restrict__ Wkv_b)
{
    const int z = blockIdx.z;
    const __half* A = (z == 0) ? g_x : g_y;
    const __half* B = (z == 0) ? g_wq : g_wkv;
    const float* bias = (z == 0) ? Wq_b : Wkv_b;
    __half* dst = (z == 0) ? g_q : (z == 1) ? g_k : g_v;
    const int csub = (z == 2) ? 1024 : 0;   // V writes at c-1024

    __shared__ __align__(128) char smraw[2 * STAGE_B];   // 48 KB static
    const uint32_t smb = smem_u32(smraw);

    const int tid = threadIdx.x;
    const int wid = tid >> 5;
    const int lane = tid & 31;
    const int m0 = blockIdx.y * 128;
    const int n0 = ((z == 2) ? 1024 : 0) + blockIdx.x * 256;
    const int warp_m = (wid & 1) * 64;
    const int warp_n = (wid >> 1) * 64;
    const float qscale = (z == 0) ? 0.125f : 1.0f;

    float acc[4][8][4];
#pragma unroll
    for (int i = 0; i < 4; ++i)
#pragma unroll
        for (int j = 0; j < 8; ++j)
#pragma unroll
            for (int c = 0; c < 4; ++c) acc[i][j][c] = 0.f;

    GEMM_MAINLOOP(A, B)

    // ---- epilogue: coalesced fp16 [m][c] stores
#pragma unroll
    for (int tm = 0; tm < 4; ++tm) {
#pragma unroll
        for (int tn = 0; tn < 8; ++tn) {
            const int rbase = m0 + warp_m + tm * 16 + (lane >> 2);
            const int c = n0 + warp_n + tn * 8 + (lane & 3) * 2;
            const float b0 = bias[c], b1 = bias[c + 1];
            const int cc = c - csub;
#pragma unroll
            for (int half = 0; half < 2; ++half) {
                const int m = rbase + half * 8;
                const float v0 = (acc[tm][tn][half * 2 + 0] + b0) * qscale;
                const float v1 = (acc[tm][tn][half * 2 + 1] + b1) * qscale;
                *(uint32_t*)(dst + (size_t)m * Cdim + cc) = pack_f16x2(v0, v1);
            }
        }
    }
}

// ---- O projection: out = g_at @ Wo^T + b, fp32 plain [m][n]. grid (4, 64).
__global__ __launch_bounds__(256)
void gemm_o(const float* __restrict__ Wo_b, float* __restrict__ out)
{
    __shared__ __align__(128) char smraw[2 * STAGE_B];
    const uint32_t smb = smem_u32(smraw);

    const int tid = threadIdx.x;
    const int wid = tid >> 5;
    const int lane = tid & 31;
    const int m0 = blockIdx.y * 128;
    const int n0 = blockIdx.x * 256;
    const int warp_m = (wid & 1) * 64;
    const int warp_n = (wid >> 1) * 64;

    float acc[4][8][4];
#pragma unroll
    for (int i = 0; i < 4; ++i)
#pragma unroll
        for (int j = 0; j < 8; ++j)
#pragma unroll
            for (int c = 0; c < 4; ++c) acc[i][j][c] = 0.f;

    GEMM_MAINLOOP(g_at, g_wo)

#pragma unroll
    for (int tm = 0; tm < 4; ++tm) {
#pragma unroll
        for (int tn = 0; tn < 8; ++tn) {
            const int rbase = m0 + warp_m + tm * 16 + (lane >> 2);
            const int c = n0 + warp_n + tn * 8 + (lane & 3) * 2;
            const float b0 = Wo_b[c], b1 = Wo_b[c + 1];
#pragma unroll
            for (int half = 0; half < 2; ++half) {
                const int m = rbase + half * 8;
                float2 o;
                o.x = acc[tm][tn][half * 2 + 0] + b0;
                o.y = acc[tm][tn][half * 2 + 1] + b1;
                *(float2*)(out + (size_t)m * Cdim + c) = o;
            }
        }
    }
}

// ---------------------------------------------------------------------------
// Tensor-core fp16 flash attention with triangle pairing.
// Q/K/V in [m][h*64+d] layout: head-h rows at stride Cdim halves, 128B each.
// grid (16, NH, B); CTA does q-block bx AND q-block (31-bx): 33 tiles each.
// ---------------------------------------------------------------------------
__global__ __launch_bounds__(128)
void attn_tc(const unsigned char* __restrict__ mask)
{
    __shared__ __align__(128) unsigned char kvraw[16384];
    __shared__ __align__(8) float maskadd[64];

    const int h  = blockIdx.y;
    const int b  = blockIdx.z;
    const int tid = threadIdx.x;
    const int wid = tid >> 5;
    const int lane = tid & 31;
    const int g = lane >> 2, t = lane & 3;

    const uint32_t smb = smem_u32(kvraw);
    const uint32_t kb = smb;
    const uint32_t vb = smb + 8192;

    // head-h base pointers in [m][c] layout
    const size_t mb0 = (size_t)b * Sdim;
    const __half* K = g_k + mb0 * Cdim + h * HD;
    const __half* V = g_v + mb0 * Cdim + h * HD;
    const unsigned char* mrow = mask + (size_t)b * Sdim;

    auto load_k = [&](int k0) {
#pragma unroll
        for (int i2 = 0; i2 < 4; ++i2) {
            const int e = i2 * 128 + tid;
            const int row = e >> 3, ch = e & 7;
            CP_ASYNC16(kb + (uint32_t)(ch * 1024 + row * 16),
                       K + (size_t)(k0 + row) * Cdim + ch * 8);
        }
        CP_COMMIT();
    };
    auto load_v = [&](int k0) {
#pragma unroll
        for (int i2 = 0; i2 < 4; ++i2) {
            const int e = i2 * 128 + tid;
            const int row = e >> 3, ch = e & 7;
            CP_ASYNC16(vb + (uint32_t)(ch * 1024 + row * 16),
                       V + (size_t)(k0 + row) * Cdim + ch * 8);
        }
        CP_COMMIT();
    };

#pragma unroll 1
    for (int sub = 0; sub < 2; ++sub) {
        const int qblk = (sub == 0) ? (int)blockIdx.x
                                    : (Sdim / 64 - 1 - (int)blockIdx.x);
        const int q0 = qblk * 64;
        const int nt = qblk + 1;
        const int qg = q0 + wid * 16 + g;
        const __half* Q = g_q + (mb0 + q0) * Cdim + h * HD;

        // ---- stage Q through K buffer, load fragments
#pragma unroll
        for (int i2 = 0; i2 < 4; ++i2) {
            const int e = i2 * 128 + tid;
            const int row = e >> 3, ch = e & 7;
            CP_ASYNC16(kb + (uint32_t)(ch * 1024 + row * 16),
                       Q + (size_t)row * Cdim + ch * 8);
        }
        CP_COMMIT(); CP_WAIT(0);
        __syncthreads();

        uint32_t qf[4][4];
        {
            const int qrow = wid * 16 + (lane & 15);
#pragma unroll
            for (int ks = 0; ks < 4; ++ks)
                ldsm_x4(qf[ks], kb + (uint32_t)((2 * ks + (lane >> 4)) * 1024 + qrow * 16));
        }
        __syncthreads();

        float oacc[8][4];
#pragma unroll
        for (int j = 0; j < 8; ++j)
#pragma unroll
            for (int c = 0; c < 4; ++c) oacc[j][c] = 0.f;
        float m0 = -1e30f, m1 = -1e30f, l0 = 0.f, l1 = 0.f;

        load_k(0);

        for (int it = 0; it < nt; ++it) {
            const int k0 = it * 64;

            CP_WAIT(0);                      // K_it resident
            if (tid < 64)
                maskadd[tid] = mrow[k0 + tid] ? -1e30f : 0.f;
            __syncthreads();
            load_v(k0);                      // V_it loads under S compute

            float sacc[8][4];
#pragma unroll
            for (int j = 0; j < 8; ++j)
#pragma unroll
                for (int c = 0; c < 4; ++c) sacc[j][c] = 0.f;

#pragma unroll
            for (int ks = 0; ks < 4; ++ks) {
                uint32_t kf[8][2];
#pragma unroll
                for (int grp = 0; grp < 4; ++grp) {
                    const uint32_t a = (uint32_t)((2 * ks + (lane >> 4)) * 1024 +
                                                  (grp * 16 + (lane & 15)) * 16);
                    uint32_t r[4];
                    ldsm_x4(r, kb + a);
                    kf[2*grp][0] = r[0]; kf[2*grp][1] = r[2];
                    kf[2*grp+1][0] = r[1]; kf[2*grp+1][1] = r[3];
                }
#pragma unroll
                for (int j = 0; j < 8; ++j)
                    mma_f16(sacc[j], qf[ks], kf[j]);
            }

            const bool diag = (k0 == q0);
            float mx0 = -1e30f, mx1 = -1e30f;
#pragma unroll
            for (int j = 0; j < 8; ++j) {
                const float2 ma = *(const float2*)&maskadd[8 * j + 2 * t];
                float s0 = sacc[j][0] + ma.x;
                float s1 = sacc[j][1] + ma.y;
                float s2 = sacc[j][2] + ma.x;
                float s3 = sacc[j][3] + ma.y;
                if (diag) {
                    const int key = k0 + 8 * j + 2 * t;
                    if (key     > qg)     s0 = -1e30f;
                    if (key + 1 > qg)     s1 = -1e30f;
                    if (key     > qg + 8) s2 = -1e30f;
                    if (key + 1 > qg + 8) s3 = -1e30f;
                }
                sacc[j][0] = s0; sacc[j][1] = s1; sacc[j][2] = s2; sacc[j][3] = s3;
                mx0 = fmaxf(mx0, fmaxf(s0, s1));
                mx1 = fmaxf(mx1, fmaxf(s2, s3));
            }
            mx0 = fmaxf(mx0, __shfl_xor_sync(0xFFFFFFFFu, mx0, 1));
            mx0 = fmaxf(mx0, __shfl_xor_sync(0xFFFFFFFFu, mx0, 2));
            mx1 = fmaxf(mx1, __shfl_xor_sync(0xFFFFFFFFu, mx1, 1));
            mx1 = fmaxf(mx1, __shfl_xor_sync(0xFFFFFFFFu, mx1, 2));
            const float mn0 = fmaxf(m0, mx0), mn1 = fmaxf(m1, mx1);
            const float cr0 = fast_exp(m0 - mn0), cr1 = fast_exp(m1 - mn1);
            m0 = mn0; m1 = mn1;
            l0 *= cr0; l1 *= cr1;
#pragma unroll
            for (int j = 0; j < 8; ++j) {
                oacc[j][0] *= cr0; oacc[j][1] *= cr0;
                oacc[j][2] *= cr1; oacc[j][3] *= cr1;
            }

            float sum0 = 0.f, sum1 = 0.f;
            uint32_t pf[4][4];
#pragma unroll
            for (int j = 0; j < 8; ++j) {
                const float p0 = fast_exp(sacc[j][0] - mn0);
                const float p1 = fast_exp(sacc[j][1] - mn0);
                const float p2 = fast_exp(sacc[j][2] - mn1);
                const float p3 = fast_exp(sacc[j][3] - mn1);
                sum0 += p0 + p1; sum1 += p2 + p3;
                const int kk = j >> 1, sl = (j & 1) * 2;
                pf[kk][sl + 0] = pack_f16x2(p0, p1);
                pf[kk][sl + 1] = pack_f16x2(p2, p3);
            }
            sum0 += __shfl_xor_sync(0xFFFFFFFFu, sum0, 1);
            sum0 += __shfl_xor_sync(0xFFFFFFFFu, sum0, 2);
            sum1 += __shfl_xor_sync(0xFFFFFFFFu, sum1, 1);
            sum1 += __shfl_xor_sync(0xFFFFFFFFu, sum1, 2);
            l0 += sum0; l1 += sum1;

            CP_WAIT(0);                      // V_it resident
            __syncthreads();
            if (it + 1 < nt) load_k(k0 + 64);

#pragma unroll
            for (int kp = 0; kp < 4; ++kp) {
                uint32_t vf[8][2];
#pragma unroll
                for (int db = 0; db < 4; ++db) {
                    const uint32_t a = (uint32_t)((2 * db + (lane >> 4)) * 1024 +
                                                  (kp * 16 + (lane & 15)) * 16);
                    uint32_t r[4];
                    ldsm_x4t(r, vb + a);
                    vf[2*db][0] = r[0]; vf[2*db][1] = r[1];
                    vf[2*db+1][0] = r[2]; vf[2*db+1][1] = r[3];
                }
#pragma unroll
                for (int j = 0; j < 8; ++j)
                    mma_f16(oacc[j], pf[kp], vf[j]);
            }
        }

        // ---- epilogue: o/l -> fp16 at [b*s + q][h*64 + d]
        const float inv0 = 1.f / l0;
        const float inv1 = 1.f / l1;
        __half* o0p = g_at + (mb0 + qg) * Cdim + h * HD;
        __half* o1p = o0p + 8 * Cdim;
#pragma unroll
        for (int j = 0; j < 8; ++j) {
            const int d = 8 * j + 2 * t;
            *(uint32_t*)(o0p + d) = pack_f16x2(oacc[j][0] * inv0, oacc[j][1] * inv0);
            *(uint32_t*)(o1p + d) = pack_f16x2(oacc[j][2] * inv1, oacc[j][3] * inv1);
        }
        __syncthreads();   // kb/vb reuse safety across sub iterations
    }
}

// ---------------------------------------------------------------------------
extern "C" void kernel_launch(void* const* d_in, const int* in_sizes, int n_in,
                              void* d_out, int out_size)
{
    const float* x     = (const float*)d_in[0];
    const float* y     = (const float*)d_in[1];
    const unsigned char* mask = (const unsigned char*)d_in[2];
    const float* Wq_b  = (const float*)d_in[4];
    const float* Wkv_b = (const float*)d_in[6];
    const float* Wo_b  = (const float*)d_in[8];
    float* out = (float*)d_out;

    convert_all<<<NTOT4 / 256, 256>>>((const float4*)x, (const float4*)y,
                                      (const float4*)d_in[3], (const float4*)d_in[5],
                                      (const float4*)d_in[7]);
    gemm_qkv<<<dim3(4, 64, 3), 256>>>(Wq_b, Wkv_b);
    attn_tc<<<dim3(Sdim / 128, NH, Bdim), 128>>>(mask);
    gemm_o<<<dim3(4, 64), 256>>>(Wo_b, out);
}